// round 8
// baseline (speedup 1.0000x reference)
#include <cuda_runtime.h>
#include <cuda_bf16.h>
#include <math.h>
#include <stdint.h>

#define E 1024
#define NH 16
#define P 64
#define BATCH 2
#define SEQ 2048
#define BS (BATCH*SEQ)          // 4096

// ---------------- device scratch ----------------
__device__ float g_lam;
__device__ float g_Wf[E*192];          // [1024,192] fused proj weights
__device__ float g_Weff[P*E];          // [64,1024]
__device__ float g_q[BS*P];            // [4096,64]  q (+bias)
__device__ float g_M[BATCH*P*P];       // [2,64,64]  K^T V
__device__ float g_G[BATCH*P*E];       // [2,64,1024] (D M) @ Weff

// ---------------- helpers ----------------
__device__ __forceinline__ void split2(float x0, float x1, uint32_t& hi, uint32_t& lo) {
    __nv_bfloat162 h = __floats2bfloat162_rn(x0, x1);
    hi = *(uint32_t*)&h;
    __nv_bfloat162 l = __floats2bfloat162_rn(x0 - __bfloat162float(h.x),
                                             x1 - __bfloat162float(h.y));
    lo = *(uint32_t*)&l;
}

#define MMA_BF16(d, a0,a1,a2,a3, b0,b1) \
    asm volatile("mma.sync.aligned.m16n8k16.row.col.f32.bf16.bf16.f32 " \
        "{%0,%1,%2,%3}, {%4,%5,%6,%7}, {%8,%9}, {%0,%1,%2,%3};" \
        : "+f"(d[0]),"+f"(d[1]),"+f"(d[2]),"+f"(d[3]) \
        : "r"(a0),"r"(a1),"r"(a2),"r"(a3), "r"(b0),"r"(b1))

// =====================================================================
// L0: zero g_Wf (blocks 0..191) + zero g_M (block 192)
// =====================================================================
__global__ void k_zero()
{
    const int bid = blockIdx.x, tid = threadIdx.x;
    if (bid < 192) {
        ((float4*)g_Wf)[bid * 256 + tid] = make_float4(0.f, 0.f, 0.f, 0.f);
    } else {
        for (int i = tid; i < BATCH*P*P; i += 256) g_M[i] = 0.f;
    }
}

// =====================================================================
// L1: blocks [0,256): Weff ; block 256: lambda ;
//     blocks [257,641): Wf split-K x8 (atomicAdd epilogue)
// =====================================================================
__global__ void __launch_bounds__(256) k_prep(
    const float* __restrict__ WQ, const float* __restrict__ WK,
    const float* __restrict__ WV, const float* __restrict__ pw,
    const float* __restrict__ RW,
    const float* __restrict__ q1v, const float* __restrict__ k1v,
    const float* __restrict__ q2v, const float* __restrict__ k2v,
    const float* __restrict__ lam0)
{
    __shared__ uint32_t AsH[8][72], AsL[8][72], BsH[8][72], BsL[8][72];
    const int bid = blockIdx.x;
    const int tid = threadIdx.x;

    if (bid < 256) {
        int idx = bid * 256 + tid;
        int q = idx >> 10, e = idx & 1023;
        float s = 0.f;
        #pragma unroll
        for (int h = 0; h < NH; h++)
            s = fmaf((float)(h + 1), RW[(size_t)((h << 6) + q) * E + e], s);
        g_Weff[idx] = s;
        return;
    }
    if (bid == 256) {
        __shared__ float s1[256], s2[256];
        float a = 0.f, b = 0.f;
        for (int i = tid; i < E; i += 256) {
            a = fmaf(q1v[i], k1v[i], a);
            b = fmaf(q2v[i], k2v[i], b);
        }
        s1[tid] = a; s2[tid] = b; __syncthreads();
        for (int o = 128; o > 0; o >>= 1) {
            if (tid < o) { s1[tid] += s1[tid+o]; s2[tid] += s2[tid+o]; }
            __syncthreads();
        }
        if (tid == 0) g_lam = expf(s1[0]) - expf(s2[0]) + lam0[0];
        return;
    }
    // ---- Wf split-K: 384 blocks = 3 mats x 16 row-tiles x 8 k-chunks ----
    const int r3   = bid - 257;
    const int mat  = r3 >> 7;
    const int chunk = (r3 & 127) >> 4;
    const int row0 = (r3 & 15) * 64;
    const float* A = ((mat == 0) ? WQ : (mat == 1) ? WK : WV) + chunk * 128;
    const float* Bbase = pw + (long)(chunk * 128) * P;
    constexpr int KT = 128;

    const int wid = tid >> 5, lane = tid & 31;
    const int wm = wid & 1, wn = wid >> 1;
    const int g = lane >> 2, t = lane & 3;
    const int n0 = wn * 16;
    const int m_l = tid >> 2, khA = (tid & 3) * 4, khA2 = khA >> 1;
    const int k2b = tid >> 5, n2 = (tid & 31) * 2;

    const float* Ap = A + (long)(row0 + m_l) * E + khA;
    const float* Bp = Bbase + (long)(2 * k2b) * P + n2;

    float rA0[4], rA1[4], rB0[4], rB1[4];
    float acc[2][2][4] = {};

    auto ldA = [&](int k0, float* r) {
        int kk = (k0 < KT) ? k0 : 0;
        float4 v = *(const float4*)(Ap + kk);
        r[0]=v.x; r[1]=v.y; r[2]=v.z; r[3]=v.w;
    };
    auto ldB = [&](int k0, float* r) {
        int kk = (k0 < KT) ? k0 : 0;
        float2 e0 = *(const float2*)(Bp + (long)kk * P);
        float2 e1 = *(const float2*)(Bp + (long)(kk + 1) * P);
        r[0]=e0.x; r[1]=e0.y; r[2]=e1.x; r[3]=e1.y;
    };
    auto stA = [&](const float* r) {
        split2(r[0], r[1], AsH[khA2  ][m_l], AsL[khA2  ][m_l]);
        split2(r[2], r[3], AsH[khA2+1][m_l], AsL[khA2+1][m_l]);
    };
    auto stB = [&](const float* r) {
        split2(r[0], r[2], BsH[k2b][n2],   BsL[k2b][n2]);
        split2(r[1], r[3], BsH[k2b][n2+1], BsL[k2b][n2+1]);
    };
    auto compute = [&]() {
        uint32_t bH[2][2], bL[2][2];
        #pragma unroll
        for (int nj = 0; nj < 2; nj++) {
            int nb = n0 + nj * 8 + g;
            bH[nj][0]=BsH[t][nb]; bH[nj][1]=BsH[t+4][nb];
            bL[nj][0]=BsL[t][nb]; bL[nj][1]=BsL[t+4][nb];
        }
        #pragma unroll
        for (int mi = 0; mi < 2; mi++) {
            int mb = wm * 32 + mi * 16 + g;
            uint32_t aH0=AsH[t][mb],   aH1=AsH[t][mb+8];
            uint32_t aH2=AsH[t+4][mb], aH3=AsH[t+4][mb+8];
            uint32_t aL0=AsL[t][mb],   aL1=AsL[t][mb+8];
            uint32_t aL2=AsL[t+4][mb], aL3=AsL[t+4][mb+8];
            #pragma unroll
            for (int nj = 0; nj < 2; nj++) {
                MMA_BF16(acc[mi][nj], aH0,aH1,aH2,aH3, bH[nj][0], bH[nj][1]);
                MMA_BF16(acc[mi][nj], aL0,aL1,aL2,aL3, bH[nj][0], bH[nj][1]);
                MMA_BF16(acc[mi][nj], aH0,aH1,aH2,aH3, bL[nj][0], bL[nj][1]);
            }
        }
    };

    ldA(0, rA0);  ldB(0, rB0);
    ldA(16, rA1); ldB(16, rB1);
    #pragma unroll 1
    for (int k0 = 0; k0 < KT; k0 += 32) {
        stA(rA0); stB(rB0); __syncthreads();
        ldA(k0 + 32, rA0); ldB(k0 + 32, rB0);
        compute(); __syncthreads();
        stA(rA1); stB(rB1); __syncthreads();
        ldA(k0 + 48, rA1); ldB(k0 + 48, rB1);
        compute(); __syncthreads();
    }
    #pragma unroll
    for (int mi = 0; mi < 2; mi++) {
        int r = row0 + wm * 32 + mi * 16 + g;
        #pragma unroll
        for (int nj = 0; nj < 2; nj++) {
            int cl = n0 + nj * 8 + 2 * t;
            atomicAdd(&g_Wf[(long)r * 192 + mat * 64 + cl],           acc[mi][nj][0]);
            atomicAdd(&g_Wf[(long)r * 192 + mat * 64 + cl + 1],       acc[mi][nj][1]);
            atomicAdd(&g_Wf[(long)(r + 8) * 192 + mat * 64 + cl],     acc[mi][nj][2]);
            atomicAdd(&g_Wf[(long)(r + 8) * 192 + mat * 64 + cl + 1], acc[mi][nj][3]);
        }
    }
}

// =====================================================================
// L2: qkv + fused ktv. grid (2, 64). Double-buffered smem (1 sync/window),
// GEMM buffers union'd with ktv staging arrays.
// =====================================================================
struct GemmBufs { uint32_t AsH[2][8][72], AsL[2][8][72], BsH[2][8][136], BsL[2][8][136]; };
struct KtvBufs  { float sKT[64][65], sV[64][65]; };

__global__ void __launch_bounds__(256) k_qkv(
    const float* __restrict__ x, const float* __restrict__ pb)
{
    __shared__ union SU { GemmBufs gb; KtvBufs kb; } su;

    const bool qb = (blockIdx.x == 0);
    const int row0 = blockIdx.y * 64;
    const int batch = blockIdx.y >> 5;
    const int colOff = qb ? 0 : 64;
    const int tid = threadIdx.x, wid = tid >> 5, lane = tid & 31;
    const int wm = wid & 1, wn = wid >> 1;      // WM=2 x WN=4, warp tile 32x32
    const int g = lane >> 2, t = lane & 3;
    const int n0 = wn * 32;
    const int m_l = tid >> 2, khA = (tid & 3) * 4, khA2 = khA >> 1;
    const int k2b = tid >> 6;                   // 0..3
    const int n2  = (tid & 63) * 2;             // 0..126

    const float* Ap = x + (long)(row0 + m_l) * E + khA;
    const float* Bp = g_Wf + colOff + n2;

    float rA[4], rB[8];
    float acc[2][4][4] = {};

    auto ldA = [&](int k0) {
        int kk = (k0 < E) ? k0 : 0;
        float4 v = *(const float4*)(Ap + kk);
        rA[0]=v.x; rA[1]=v.y; rA[2]=v.z; rA[3]=v.w;
    };
    auto ldB = [&](int k0) {
        int kk = (k0 < E) ? k0 : 0;
        float2 e0 = *(const float2*)(Bp + (long)(kk + 2*k2b    ) * 192);
        float2 e1 = *(const float2*)(Bp + (long)(kk + 2*k2b + 1) * 192);
        float2 e2 = *(const float2*)(Bp + (long)(kk + 2*k2b + 8) * 192);
        float2 e3 = *(const float2*)(Bp + (long)(kk + 2*k2b + 9) * 192);
        rB[0]=e0.x; rB[1]=e0.y; rB[2]=e1.x; rB[3]=e1.y;
        rB[4]=e2.x; rB[5]=e2.y; rB[6]=e3.x; rB[7]=e3.y;
    };
    auto stAB = [&](int buf) {
        split2(rA[0], rA[1], su.gb.AsH[buf][khA2  ][m_l], su.gb.AsL[buf][khA2  ][m_l]);
        split2(rA[2], rA[3], su.gb.AsH[buf][khA2+1][m_l], su.gb.AsL[buf][khA2+1][m_l]);
        split2(rB[0], rB[2], su.gb.BsH[buf][k2b  ][n2],   su.gb.BsL[buf][k2b  ][n2]);
        split2(rB[1], rB[3], su.gb.BsH[buf][k2b  ][n2+1], su.gb.BsL[buf][k2b  ][n2+1]);
        split2(rB[4], rB[6], su.gb.BsH[buf][k2b+4][n2],   su.gb.BsL[buf][k2b+4][n2]);
        split2(rB[5], rB[7], su.gb.BsH[buf][k2b+4][n2+1], su.gb.BsL[buf][k2b+4][n2+1]);
    };
    auto compute = [&](int buf) {
        uint32_t bH[4][2], bL[4][2];
        #pragma unroll
        for (int nj = 0; nj < 4; nj++) {
            int nb = n0 + nj * 8 + g;
            bH[nj][0]=su.gb.BsH[buf][t][nb]; bH[nj][1]=su.gb.BsH[buf][t+4][nb];
            bL[nj][0]=su.gb.BsL[buf][t][nb]; bL[nj][1]=su.gb.BsL[buf][t+4][nb];
        }
        #pragma unroll
        for (int mi = 0; mi < 2; mi++) {
            int mb = wm * 32 + mi * 16 + g;
            uint32_t aH0=su.gb.AsH[buf][t][mb],   aH1=su.gb.AsH[buf][t][mb+8];
            uint32_t aH2=su.gb.AsH[buf][t+4][mb], aH3=su.gb.AsH[buf][t+4][mb+8];
            uint32_t aL0=su.gb.AsL[buf][t][mb],   aL1=su.gb.AsL[buf][t][mb+8];
            uint32_t aL2=su.gb.AsL[buf][t+4][mb], aL3=su.gb.AsL[buf][t+4][mb+8];
            #pragma unroll
            for (int nj = 0; nj < 4; nj++) {
                MMA_BF16(acc[mi][nj], aH0,aH1,aH2,aH3, bH[nj][0], bH[nj][1]);
                MMA_BF16(acc[mi][nj], aL0,aL1,aL2,aL3, bH[nj][0], bH[nj][1]);
                MMA_BF16(acc[mi][nj], aH0,aH1,aH2,aH3, bL[nj][0], bL[nj][1]);
            }
        }
    };

    ldA(0); ldB(0);
    #pragma unroll 1
    for (int w = 0; w < 64; w++) {
        int buf = w & 1;
        stAB(buf);
        __syncthreads();
        ldA((w + 1) * 16); ldB((w + 1) * 16);
        compute(buf);
    }
    __syncthreads();   // all compute done before union reuse / epilogue

    if (qb) {
        #pragma unroll
        for (int mi = 0; mi < 2; mi++) {
            int r = row0 + wm * 32 + mi * 16 + g;
            #pragma unroll
            for (int nj = 0; nj < 4; nj++) {
                int cl = n0 + nj * 8 + 2 * t;
                if (cl < 64) {
                    float b0 = pb[cl], b1 = pb[cl + 1];
                    *(float2*)&g_q[(long)r * P + cl] =
                        make_float2(acc[mi][nj][0] + b0, acc[mi][nj][1] + b1);
                    *(float2*)&g_q[(long)(r + 8) * P + cl] =
                        make_float2(acc[mi][nj][2] + b0, acc[mi][nj][3] + b1);
                }
            }
        }
    } else {
        // stage k (transposed) + v into union'd smem
        #pragma unroll
        for (int mi = 0; mi < 2; mi++) {
            int tok = wm * 32 + mi * 16 + g;
            #pragma unroll
            for (int nj = 0; nj < 4; nj++) {
                int cl = n0 + nj * 8 + 2 * t;
                float b0 = pb[cl & 63], b1 = pb[(cl + 1) & 63];
                float v00 = acc[mi][nj][0] + b0, v01 = acc[mi][nj][1] + b1;
                float v10 = acc[mi][nj][2] + b0, v11 = acc[mi][nj][3] + b1;
                if (cl < 64) {
                    su.kb.sKT[cl  ][tok]   = v00; su.kb.sKT[cl+1][tok]   = v01;
                    su.kb.sKT[cl  ][tok+8] = v10; su.kb.sKT[cl+1][tok+8] = v11;
                } else {
                    su.kb.sV[tok  ][cl-64] = v00; su.kb.sV[tok  ][cl-63] = v01;
                    su.kb.sV[tok+8][cl-64] = v10; su.kb.sV[tok+8][cl-63] = v11;
                }
            }
        }
        __syncthreads();
        float acc2[2][2][4] = {};
        #pragma unroll
        for (int w = 0; w < 4; w++) {
            int b0k = w * 16;
            uint32_t bH[2][2], bL[2][2];
            #pragma unroll
            for (int nj = 0; nj < 2; nj++) {
                int nb = wn * 16 + nj * 8 + g;
                split2(su.kb.sV[b0k+2*t  ][nb], su.kb.sV[b0k+2*t+1][nb], bH[nj][0], bL[nj][0]);
                split2(su.kb.sV[b0k+2*t+8][nb], su.kb.sV[b0k+2*t+9][nb], bH[nj][1], bL[nj][1]);
            }
            #pragma unroll
            for (int mi = 0; mi < 2; mi++) {
                int mb = wm * 32 + mi * 16 + g;
                uint32_t aH0,aL0,aH1,aL1,aH2,aL2,aH3,aL3;
                split2(su.kb.sKT[mb  ][b0k+2*t  ], su.kb.sKT[mb  ][b0k+2*t+1], aH0, aL0);
                split2(su.kb.sKT[mb+8][b0k+2*t  ], su.kb.sKT[mb+8][b0k+2*t+1], aH1, aL1);
                split2(su.kb.sKT[mb  ][b0k+2*t+8], su.kb.sKT[mb  ][b0k+2*t+9], aH2, aL2);
                split2(su.kb.sKT[mb+8][b0k+2*t+8], su.kb.sKT[mb+8][b0k+2*t+9], aH3, aL3);
                #pragma unroll
                for (int nj = 0; nj < 2; nj++) {
                    MMA_BF16(acc2[mi][nj], aH0,aH1,aH2,aH3, bH[nj][0], bH[nj][1]);
                    MMA_BF16(acc2[mi][nj], aL0,aL1,aL2,aL3, bH[nj][0], bH[nj][1]);
                    MMA_BF16(acc2[mi][nj], aH0,aH1,aH2,aH3, bL[nj][0], bL[nj][1]);
                }
            }
        }
        float* M = g_M + batch * P * P;
        #pragma unroll
        for (int mi = 0; mi < 2; mi++) {
            int kc = wm * 32 + mi * 16 + g;
            #pragma unroll
            for (int nj = 0; nj < 2; nj++) {
                int vc = wn * 16 + nj * 8 + 2 * t;
                atomicAdd(&M[kc * P + vc],           acc2[mi][nj][0]);
                atomicAdd(&M[kc * P + vc + 1],       acc2[mi][nj][1]);
                atomicAdd(&M[(kc + 8) * P + vc],     acc2[mi][nj][2]);
                atomicAdd(&M[(kc + 8) * P + vc + 1], acc2[mi][nj][3]);
            }
        }
    }
}

// =====================================================================
// L2b: G_b = (D M_b) @ Weff.  grid (16, 1, 2) = 32 blocks. BM=64,N=64,K=64.
// =====================================================================
__global__ void __launch_bounds__(256) k_G()
{
    __shared__ uint32_t AsH[32][72], AsL[32][72];
    __shared__ uint32_t BsH[2][8][72], BsL[2][8][72];

    const int col0 = blockIdx.x * 64;
    const int batch = blockIdx.z;
    const int tid = threadIdx.x, wid = tid >> 5, lane = tid & 31;
    const int wm = wid & 1, wn = wid >> 1;   // WM=2 x WN=4, warp tile 32x16
    const int g = lane >> 2, t = lane & 3;
    const int n0 = wn * 16;
    const int m_l = tid >> 2, khA = (tid & 3) * 4;
    const int k2b = tid >> 5, n2 = (tid & 31) * 2;
    const float lam = g_lam;
    const float sclA = (m_l < 32) ? 0.125f : (-lam * 0.125f);

    // A = (D M): all 4 windows into As
    const float* Mp = g_M + batch * P * P + (long)m_l * P + khA;
    #pragma unroll
    for (int w = 0; w < 4; w++) {
        float4 v = *(const float4*)(Mp + w * 16);
        int kp = w * 8 + (khA >> 1);
        split2(v.x * sclA, v.y * sclA, AsH[kp  ][m_l], AsL[kp  ][m_l]);
        split2(v.z * sclA, v.w * sclA, AsH[kp+1][m_l], AsL[kp+1][m_l]);
    }
    // B = Weff tile: prefetch all windows to regs
    const float* Wp = g_Weff + col0 + n2;
    float rB[4][4];
    #pragma unroll
    for (int w = 0; w < 4; w++) {
        int kr = w * 16 + 2 * k2b;
        float2 e0 = *(const float2*)(Wp + (long)kr * E);
        float2 e1 = *(const float2*)(Wp + (long)(kr + 1) * E);
        rB[w][0]=e0.x; rB[w][1]=e0.y; rB[w][2]=e1.x; rB[w][3]=e1.y;
    }

    float acc[2][2][4] = {};
    #pragma unroll
    for (int w = 0; w < 4; w++) {
        int buf = w & 1;
        split2(rB[w][0], rB[w][2], BsH[buf][k2b][n2],   BsL[buf][k2b][n2]);
        split2(rB[w][1], rB[w][3], BsH[buf][k2b][n2+1], BsL[buf][k2b][n2+1]);
        __syncthreads();
        uint32_t bH[2][2], bL[2][2];
        #pragma unroll
        for (int nj = 0; nj < 2; nj++) {
            int nb = n0 + nj * 8 + g;
            bH[nj][0]=BsH[buf][t][nb]; bH[nj][1]=BsH[buf][t+4][nb];
            bL[nj][0]=BsL[buf][t][nb]; bL[nj][1]=BsL[buf][t+4][nb];
        }
        #pragma unroll
        for (int mi = 0; mi < 2; mi++) {
            int mb = wm * 32 + mi * 16 + g;
            uint32_t aH0=AsH[w*8+t  ][mb], aH1=AsH[w*8+t  ][mb+8];
            uint32_t aH2=AsH[w*8+t+4][mb], aH3=AsH[w*8+t+4][mb+8];
            uint32_t aL0=AsL[w*8+t  ][mb], aL1=AsL[w*8+t  ][mb+8];
            uint32_t aL2=AsL[w*8+t+4][mb], aL3=AsL[w*8+t+4][mb+8];
            #pragma unroll
            for (int nj = 0; nj < 2; nj++) {
                MMA_BF16(acc[mi][nj], aH0,aH1,aH2,aH3, bH[nj][0], bH[nj][1]);
                MMA_BF16(acc[mi][nj], aL0,aL1,aL2,aL3, bH[nj][0], bH[nj][1]);
                MMA_BF16(acc[mi][nj], aH0,aH1,aH2,aH3, bL[nj][0], bL[nj][1]);
            }
        }
    }
    float* Gp = g_G + (long)batch * P * E;
    #pragma unroll
    for (int mi = 0; mi < 2; mi++) {
        int r = wm * 32 + mi * 16 + g;
        #pragma unroll
        for (int nj = 0; nj < 2; nj++) {
            int cl = n0 + nj * 8 + 2 * t;
            *(float2*)&Gp[(long)r * E + col0 + cl] =
                make_float2(acc[mi][nj][0], acc[mi][nj][1]);
            *(float2*)&Gp[(long)(r + 8) * E + col0 + cl] =
                make_float2(acc[mi][nj][2], acc[mi][nj][3]);
        }
    }
}

// =====================================================================
// L3: out = q @ G_batch. grid (16, 32), BM=128 x 64 cols, K=64. Single phase.
// =====================================================================
__global__ void __launch_bounds__(256) k_out(float* __restrict__ out)
{
    __shared__ uint32_t AsH[32][136], AsL[32][136];
    __shared__ uint32_t BsH[2][8][72], BsL[2][8][72];

    const int row0 = blockIdx.y * 128;
    const int col0 = blockIdx.x * 64;
    const int batch = blockIdx.y >> 4;
    const int tid = threadIdx.x, wid = tid >> 5, lane = tid & 31;
    const int wm = wid & 3, wn = wid >> 2;   // WM=4 x WN=2, warp tile 32x32
    const int g = lane >> 2, t = lane & 3;
    const int n0 = wn * 32;
    const int m_l = tid >> 1, khA = (tid & 1) * 8;
    const int k2b = tid >> 5, n2 = (tid & 31) * 2;

    // A = q rows (full K=64)
    const float* Ap = g_q + (long)(row0 + m_l) * P + khA;
    #pragma unroll
    for (int w = 0; w < 4; w++) {
        float4 v0 = *(const float4*)(Ap + w * 16);
        float4 v1 = *(const float4*)(Ap + w * 16 + 4);
        int kp = w * 8 + (khA >> 1);
        split2(v0.x, v0.y, AsH[kp  ][m_l], AsL[kp  ][m_l]);
        split2(v0.z, v0.w, AsH[kp+1][m_l], AsL[kp+1][m_l]);
        split2(v1.x, v1.y, AsH[kp+2][m_l], AsL[kp+2][m_l]);
        split2(v1.z, v1.w, AsH[kp+3][m_l], AsL[kp+3][m_l]);
    }
    // B = G tile: prefetch all windows
    const float* Gp = g_G + (long)batch * P * E + col0 + n2;
    float rB[4][4];
    #pragma unroll
    for (int w = 0; w < 4; w++) {
        int kr = w * 16 + 2 * k2b;
        float2 e0 = *(const float2*)(Gp + (long)kr * E);
        float2 e1 = *(const float2*)(Gp + (long)(kr + 1) * E);
        rB[w][0]=e0.x; rB[w][1]=e0.y; rB[w][2]=e1.x; rB[w][3]=e1.y;
    }

    float acc[2][4][4] = {};
    #pragma unroll
    for (int w = 0; w < 4; w++) {
        int buf = w & 1;
        split2(rB[w][0], rB[w][2], BsH[buf][k2b][n2],   BsL[buf][k2b][n2]);
        split2(rB[w][1], rB[w][3], BsH[buf][k2b][n2+1], BsL[buf][k2b][n2+1]);
        __syncthreads();
        uint32_t bH[4][2], bL[4][2];
        #pragma unroll
        for (int nj = 0; nj < 4; nj++) {
            int nb = n0 + nj * 8 + g;
            bH[nj][0]=BsH[buf][t][nb]; bH[nj][1]=BsH[buf][t+4][nb];
            bL[nj][0]=BsL[buf][t][nb]; bL[nj][1]=BsL[buf][t+4][nb];
        }
        #pragma unroll
        for (int mi = 0; mi < 2; mi++) {
            int mb = wm * 32 + mi * 16 + g;
            uint32_t aH0=AsH[w*8+t  ][mb], aH1=AsH[w*8+t  ][mb+8];
            uint32_t aH2=AsH[w*8+t+4][mb], aH3=AsH[w*8+t+4][mb+8];
            uint32_t aL0=AsL[w*8+t  ][mb], aL1=AsL[w*8+t  ][mb+8];
            uint32_t aL2=AsL[w*8+t+4][mb], aL3=AsL[w*8+t+4][mb+8];
            #pragma unroll
            for (int nj = 0; nj < 4; nj++) {
                MMA_BF16(acc[mi][nj], aH0,aH1,aH2,aH3, bH[nj][0], bH[nj][1]);
                MMA_BF16(acc[mi][nj], aL0,aL1,aL2,aL3, bH[nj][0], bH[nj][1]);
                MMA_BF16(acc[mi][nj], aH0,aH1,aH2,aH3, bL[nj][0], bL[nj][1]);
            }
        }
    }
    #pragma unroll
    for (int mi = 0; mi < 2; mi++) {
        int r = row0 + wm * 32 + mi * 16 + g;
        #pragma unroll
        for (int nj = 0; nj < 4; nj++) {
            int cl = n0 + nj * 8 + 2 * t;
            *(float2*)&out[(long)r * E + col0 + cl] =
                make_float2(acc[mi][nj][0], acc[mi][nj][1]);
            *(float2*)&out[(long)(r + 8) * E + col0 + cl] =
                make_float2(acc[mi][nj][2], acc[mi][nj][3]);
        }
    }
}

// ---------------- launch ----------------
extern "C" void kernel_launch(void* const* d_in, const int* in_sizes, int n_in,
                              void* d_out, int out_size)
{
    const float* x    = (const float*)d_in[0];
    const float* WQ   = (const float*)d_in[1];
    const float* WK   = (const float*)d_in[2];
    const float* WV   = (const float*)d_in[3];
    const float* RW   = (const float*)d_in[4];
    const float* pw   = (const float*)d_in[5];
    const float* pb   = (const float*)d_in[6];
    const float* q1v  = (const float*)d_in[7];
    const float* k1v  = (const float*)d_in[8];
    const float* q2v  = (const float*)d_in[9];
    const float* k2v  = (const float*)d_in[10];
    const float* lam0 = (const float*)d_in[11];
    float* out = (float*)d_out;

    // L0: zero Wf + M
    k_zero<<<193, 256>>>();

    // L1: Weff + lambda + Wf split-K x8
    k_prep<<<641, 256>>>(WQ, WK, WV, pw, RW, q1v, k1v, q2v, k2v, lam0);

    // L2: qkv + fused ktv
    k_qkv<<<dim3(2, 64), 256>>>(x, pb);

    // L2b: G = (D M) @ Weff
    k_G<<<dim3(16, 1, 2), 256>>>();

    // L3: out = q @ G
    k_out<<<dim3(16, 32), 256>>>(out);

    (void)in_sizes; (void)n_in; (void)out_size;
}

// round 9
// speedup vs baseline: 1.1349x; 1.1349x over previous
#include <cuda_runtime.h>
#include <cuda_bf16.h>
#include <math.h>
#include <stdint.h>

#define E 1024
#define NH 16
#define P 64
#define BATCH 2
#define SEQ 2048
#define BS (BATCH*SEQ)          // 4096

// ---------------- device scratch ----------------
__device__ float g_lam;
__device__ float g_Wf[E*192];          // [1024,192] fused proj weights
__device__ float g_Weff[P*E];          // [64,1024]
__device__ float g_q[BS*P];            // [4096,64]  q (+bias)
__device__ float g_M[BATCH*P*P];       // [2,64,64]  K^T V

// ---------------- helpers ----------------
__device__ __forceinline__ void split2(float x0, float x1, uint32_t& hi, uint32_t& lo) {
    __nv_bfloat162 h = __floats2bfloat162_rn(x0, x1);
    hi = *(uint32_t*)&h;
    __nv_bfloat162 l = __floats2bfloat162_rn(x0 - __bfloat162float(h.x),
                                             x1 - __bfloat162float(h.y));
    lo = *(uint32_t*)&l;
}

#define MMA_BF16(d, a0,a1,a2,a3, b0,b1) \
    asm volatile("mma.sync.aligned.m16n8k16.row.col.f32.bf16.bf16.f32 " \
        "{%0,%1,%2,%3}, {%4,%5,%6,%7}, {%8,%9}, {%0,%1,%2,%3};" \
        : "+f"(d[0]),"+f"(d[1]),"+f"(d[2]),"+f"(d[3]) \
        : "r"(a0),"r"(a1),"r"(a2),"r"(a3), "r"(b0),"r"(b1))

// =====================================================================
// L0: zero g_Wf (blocks 0..191) + zero g_M (block 192)
// =====================================================================
__global__ void k_zero()
{
    const int bid = blockIdx.x, tid = threadIdx.x;
    if (bid < 192) {
        ((float4*)g_Wf)[bid * 256 + tid] = make_float4(0.f, 0.f, 0.f, 0.f);
    } else {
        for (int i = tid; i < BATCH*P*P; i += 256) g_M[i] = 0.f;
    }
}

// =====================================================================
// L1: blocks [0,256): Weff ; block 256: lambda ;
//     blocks [257,641): Wf split-K x8 (atomicAdd epilogue)
// =====================================================================
__global__ void __launch_bounds__(256) k_prep(
    const float* __restrict__ WQ, const float* __restrict__ WK,
    const float* __restrict__ WV, const float* __restrict__ pw,
    const float* __restrict__ RW,
    const float* __restrict__ q1v, const float* __restrict__ k1v,
    const float* __restrict__ q2v, const float* __restrict__ k2v,
    const float* __restrict__ lam0)
{
    __shared__ uint32_t AsH[8][72], AsL[8][72], BsH[8][72], BsL[8][72];
    const int bid = blockIdx.x;
    const int tid = threadIdx.x;

    if (bid < 256) {
        int idx = bid * 256 + tid;
        int q = idx >> 10, e = idx & 1023;
        float s = 0.f;
        #pragma unroll
        for (int h = 0; h < NH; h++)
            s = fmaf((float)(h + 1), RW[(size_t)((h << 6) + q) * E + e], s);
        g_Weff[idx] = s;
        return;
    }
    if (bid == 256) {
        __shared__ float s1[256], s2[256];
        float a = 0.f, b = 0.f;
        for (int i = tid; i < E; i += 256) {
            a = fmaf(q1v[i], k1v[i], a);
            b = fmaf(q2v[i], k2v[i], b);
        }
        s1[tid] = a; s2[tid] = b; __syncthreads();
        for (int o = 128; o > 0; o >>= 1) {
            if (tid < o) { s1[tid] += s1[tid+o]; s2[tid] += s2[tid+o]; }
            __syncthreads();
        }
        if (tid == 0) g_lam = expf(s1[0]) - expf(s2[0]) + lam0[0];
        return;
    }
    // ---- Wf split-K: 384 blocks = 3 mats x 16 row-tiles x 8 k-chunks ----
    const int r3   = bid - 257;
    const int mat  = r3 >> 7;
    const int chunk = (r3 & 127) >> 4;
    const int row0 = (r3 & 15) * 64;
    const float* A = ((mat == 0) ? WQ : (mat == 1) ? WK : WV) + chunk * 128;
    const float* Bbase = pw + (long)(chunk * 128) * P;
    constexpr int KT = 128;

    const int wid = tid >> 5, lane = tid & 31;
    const int wm = wid & 1, wn = wid >> 1;
    const int g = lane >> 2, t = lane & 3;
    const int n0 = wn * 16;
    const int m_l = tid >> 2, khA = (tid & 3) * 4, khA2 = khA >> 1;
    const int k2b = tid >> 5, n2 = (tid & 31) * 2;

    const float* Ap = A + (long)(row0 + m_l) * E + khA;
    const float* Bp = Bbase + (long)(2 * k2b) * P + n2;

    float rA0[4], rA1[4], rB0[4], rB1[4];
    float acc[2][2][4] = {};

    auto ldA = [&](int k0, float* r) {
        int kk = (k0 < KT) ? k0 : 0;
        float4 v = *(const float4*)(Ap + kk);
        r[0]=v.x; r[1]=v.y; r[2]=v.z; r[3]=v.w;
    };
    auto ldB = [&](int k0, float* r) {
        int kk = (k0 < KT) ? k0 : 0;
        float2 e0 = *(const float2*)(Bp + (long)kk * P);
        float2 e1 = *(const float2*)(Bp + (long)(kk + 1) * P);
        r[0]=e0.x; r[1]=e0.y; r[2]=e1.x; r[3]=e1.y;
    };
    auto stA = [&](const float* r) {
        split2(r[0], r[1], AsH[khA2  ][m_l], AsL[khA2  ][m_l]);
        split2(r[2], r[3], AsH[khA2+1][m_l], AsL[khA2+1][m_l]);
    };
    auto stB = [&](const float* r) {
        split2(r[0], r[2], BsH[k2b][n2],   BsL[k2b][n2]);
        split2(r[1], r[3], BsH[k2b][n2+1], BsL[k2b][n2+1]);
    };
    auto compute = [&]() {
        uint32_t bH[2][2], bL[2][2];
        #pragma unroll
        for (int nj = 0; nj < 2; nj++) {
            int nb = n0 + nj * 8 + g;
            bH[nj][0]=BsH[t][nb]; bH[nj][1]=BsH[t+4][nb];
            bL[nj][0]=BsL[t][nb]; bL[nj][1]=BsL[t+4][nb];
        }
        #pragma unroll
        for (int mi = 0; mi < 2; mi++) {
            int mb = wm * 32 + mi * 16 + g;
            uint32_t aH0=AsH[t][mb],   aH1=AsH[t][mb+8];
            uint32_t aH2=AsH[t+4][mb], aH3=AsH[t+4][mb+8];
            uint32_t aL0=AsL[t][mb],   aL1=AsL[t][mb+8];
            uint32_t aL2=AsL[t+4][mb], aL3=AsL[t+4][mb+8];
            #pragma unroll
            for (int nj = 0; nj < 2; nj++) {
                MMA_BF16(acc[mi][nj], aH0,aH1,aH2,aH3, bH[nj][0], bH[nj][1]);
                MMA_BF16(acc[mi][nj], aL0,aL1,aL2,aL3, bH[nj][0], bH[nj][1]);
                MMA_BF16(acc[mi][nj], aH0,aH1,aH2,aH3, bL[nj][0], bL[nj][1]);
            }
        }
    };

    ldA(0, rA0);  ldB(0, rB0);
    ldA(16, rA1); ldB(16, rB1);
    #pragma unroll 1
    for (int k0 = 0; k0 < KT; k0 += 32) {
        stA(rA0); stB(rB0); __syncthreads();
        ldA(k0 + 32, rA0); ldB(k0 + 32, rB0);
        compute(); __syncthreads();
        stA(rA1); stB(rB1); __syncthreads();
        ldA(k0 + 48, rA1); ldB(k0 + 48, rB1);
        compute(); __syncthreads();
    }
    #pragma unroll
    for (int mi = 0; mi < 2; mi++) {
        int r = row0 + wm * 32 + mi * 16 + g;
        #pragma unroll
        for (int nj = 0; nj < 2; nj++) {
            int cl = n0 + nj * 8 + 2 * t;
            atomicAdd(&g_Wf[(long)r * 192 + mat * 64 + cl],           acc[mi][nj][0]);
            atomicAdd(&g_Wf[(long)r * 192 + mat * 64 + cl + 1],       acc[mi][nj][1]);
            atomicAdd(&g_Wf[(long)(r + 8) * 192 + mat * 64 + cl],     acc[mi][nj][2]);
            atomicAdd(&g_Wf[(long)(r + 8) * 192 + mat * 64 + cl + 1], acc[mi][nj][3]);
        }
    }
}

// =====================================================================
// L2: qkv + fused ktv. grid (2, 64).  (round-7 version: deep prefetch)
// =====================================================================
__global__ void __launch_bounds__(256) k_qkv(
    const float* __restrict__ x, const float* __restrict__ pb)
{
    __shared__ uint32_t AsH[8][72],  AsL[8][72];
    __shared__ uint32_t BsH[8][136], BsL[8][136];
    __shared__ float sKT[64][65];   // [kcol][token]
    __shared__ float sV[64][65];    // [token][vcol]

    const bool qb = (blockIdx.x == 0);
    const int row0 = blockIdx.y * 64;
    const int batch = blockIdx.y >> 5;
    const int colOff = qb ? 0 : 64;
    const int tid = threadIdx.x, wid = tid >> 5, lane = tid & 31;
    const int wm = wid & 1, wn = wid >> 1;      // WM=2 x WN=4, warp tile 32x32
    const int g = lane >> 2, t = lane & 3;
    const int n0 = wn * 32;
    const int m_l = tid >> 2, khA = (tid & 3) * 4, khA2 = khA >> 1;
    const int k2b = tid >> 6;                   // 0..3
    const int n2  = (tid & 63) * 2;             // 0..126

    const float* Ap = x + (long)(row0 + m_l) * E + khA;
    const float* Bp = g_Wf + colOff + n2;

    float rA0[4], rA1[4], rB0[8], rB1[8];
    float acc[2][4][4] = {};

    auto ldA = [&](int k0, float* r) {
        int kk = (k0 < E) ? k0 : 0;
        float4 v = *(const float4*)(Ap + kk);
        r[0]=v.x; r[1]=v.y; r[2]=v.z; r[3]=v.w;
    };
    auto ldB = [&](int k0, float* r) {
        int kk = (k0 < E) ? k0 : 0;
        float2 e0 = *(const float2*)(Bp + (long)(kk + 2*k2b    ) * 192);
        float2 e1 = *(const float2*)(Bp + (long)(kk + 2*k2b + 1) * 192);
        float2 e2 = *(const float2*)(Bp + (long)(kk + 2*k2b + 8) * 192);
        float2 e3 = *(const float2*)(Bp + (long)(kk + 2*k2b + 9) * 192);
        r[0]=e0.x; r[1]=e0.y; r[2]=e1.x; r[3]=e1.y;
        r[4]=e2.x; r[5]=e2.y; r[6]=e3.x; r[7]=e3.y;
    };
    auto stA = [&](const float* r) {
        split2(r[0], r[1], AsH[khA2  ][m_l], AsL[khA2  ][m_l]);
        split2(r[2], r[3], AsH[khA2+1][m_l], AsL[khA2+1][m_l]);
    };
    auto stB = [&](const float* r) {
        split2(r[0], r[2], BsH[k2b  ][n2],   BsL[k2b  ][n2]);
        split2(r[1], r[3], BsH[k2b  ][n2+1], BsL[k2b  ][n2+1]);
        split2(r[4], r[6], BsH[k2b+4][n2],   BsL[k2b+4][n2]);
        split2(r[5], r[7], BsH[k2b+4][n2+1], BsL[k2b+4][n2+1]);
    };
    auto compute = [&]() {
        uint32_t bH[4][2], bL[4][2];
        #pragma unroll
        for (int nj = 0; nj < 4; nj++) {
            int nb = n0 + nj * 8 + g;
            bH[nj][0]=BsH[t][nb]; bH[nj][1]=BsH[t+4][nb];
            bL[nj][0]=BsL[t][nb]; bL[nj][1]=BsL[t+4][nb];
        }
        #pragma unroll
        for (int mi = 0; mi < 2; mi++) {
            int mb = wm * 32 + mi * 16 + g;
            uint32_t aH0=AsH[t][mb],   aH1=AsH[t][mb+8];
            uint32_t aH2=AsH[t+4][mb], aH3=AsH[t+4][mb+8];
            uint32_t aL0=AsL[t][mb],   aL1=AsL[t][mb+8];
            uint32_t aL2=AsL[t+4][mb], aL3=AsL[t+4][mb+8];
            #pragma unroll
            for (int nj = 0; nj < 4; nj++) {
                MMA_BF16(acc[mi][nj], aH0,aH1,aH2,aH3, bH[nj][0], bH[nj][1]);
                MMA_BF16(acc[mi][nj], aL0,aL1,aL2,aL3, bH[nj][0], bH[nj][1]);
                MMA_BF16(acc[mi][nj], aH0,aH1,aH2,aH3, bL[nj][0], bL[nj][1]);
            }
        }
    };

    ldA(0, rA0);  ldB(0, rB0);
    ldA(16, rA1); ldB(16, rB1);
    #pragma unroll 1
    for (int k0 = 0; k0 < E; k0 += 32) {
        stA(rA0); stB(rB0); __syncthreads();
        ldA(k0 + 32, rA0); ldB(k0 + 32, rB0);
        compute(); __syncthreads();
        stA(rA1); stB(rB1); __syncthreads();
        ldA(k0 + 48, rA1); ldB(k0 + 48, rB1);
        compute(); __syncthreads();
    }

    if (qb) {
        #pragma unroll
        for (int mi = 0; mi < 2; mi++) {
            int r = row0 + wm * 32 + mi * 16 + g;
            #pragma unroll
            for (int nj = 0; nj < 4; nj++) {
                int cl = n0 + nj * 8 + 2 * t;
                if (cl < 64) {
                    float b0 = pb[cl], b1 = pb[cl + 1];
                    *(float2*)&g_q[(long)r * P + cl] =
                        make_float2(acc[mi][nj][0] + b0, acc[mi][nj][1] + b1);
                    *(float2*)&g_q[(long)(r + 8) * P + cl] =
                        make_float2(acc[mi][nj][2] + b0, acc[mi][nj][3] + b1);
                }
            }
        }
    } else {
        #pragma unroll
        for (int mi = 0; mi < 2; mi++) {
            int tok = wm * 32 + mi * 16 + g;
            #pragma unroll
            for (int nj = 0; nj < 4; nj++) {
                int cl = n0 + nj * 8 + 2 * t;
                float b0 = pb[cl & 63], b1 = pb[(cl + 1) & 63];
                float v00 = acc[mi][nj][0] + b0, v01 = acc[mi][nj][1] + b1;
                float v10 = acc[mi][nj][2] + b0, v11 = acc[mi][nj][3] + b1;
                if (cl < 64) {
                    sKT[cl  ][tok]   = v00; sKT[cl+1][tok]   = v01;
                    sKT[cl  ][tok+8] = v10; sKT[cl+1][tok+8] = v11;
                } else {
                    sV[tok  ][cl-64] = v00; sV[tok  ][cl-63] = v01;
                    sV[tok+8][cl-64] = v10; sV[tok+8][cl-63] = v11;
                }
            }
        }
        __syncthreads();
        float acc2[2][2][4] = {};
        #pragma unroll
        for (int w = 0; w < 4; w++) {
            int b0k = w * 16;
            uint32_t bH[2][2], bL[2][2];
            #pragma unroll
            for (int nj = 0; nj < 2; nj++) {
                int nb = wn * 16 + nj * 8 + g;
                split2(sV[b0k+2*t  ][nb], sV[b0k+2*t+1][nb], bH[nj][0], bL[nj][0]);
                split2(sV[b0k+2*t+8][nb], sV[b0k+2*t+9][nb], bH[nj][1], bL[nj][1]);
            }
            #pragma unroll
            for (int mi = 0; mi < 2; mi++) {
                int mb = wm * 32 + mi * 16 + g;
                uint32_t aH0,aL0,aH1,aL1,aH2,aL2,aH3,aL3;
                split2(sKT[mb  ][b0k+2*t  ], sKT[mb  ][b0k+2*t+1], aH0, aL0);
                split2(sKT[mb+8][b0k+2*t  ], sKT[mb+8][b0k+2*t+1], aH1, aL1);
                split2(sKT[mb  ][b0k+2*t+8], sKT[mb  ][b0k+2*t+9], aH2, aL2);
                split2(sKT[mb+8][b0k+2*t+8], sKT[mb+8][b0k+2*t+9], aH3, aL3);
                #pragma unroll
                for (int nj = 0; nj < 2; nj++) {
                    MMA_BF16(acc2[mi][nj], aH0,aH1,aH2,aH3, bH[nj][0], bH[nj][1]);
                    MMA_BF16(acc2[mi][nj], aL0,aL1,aL2,aL3, bH[nj][0], bH[nj][1]);
                    MMA_BF16(acc2[mi][nj], aH0,aH1,aH2,aH3, bL[nj][0], bL[nj][1]);
                }
            }
        }
        float* M = g_M + batch * P * P;
        #pragma unroll
        for (int mi = 0; mi < 2; mi++) {
            int kc = wm * 32 + mi * 16 + g;
            #pragma unroll
            for (int nj = 0; nj < 2; nj++) {
                int vc = wn * 16 + nj * 8 + 2 * t;
                atomicAdd(&M[kc * P + vc],           acc2[mi][nj][0]);
                atomicAdd(&M[kc * P + vc + 1],       acc2[mi][nj][1]);
                atomicAdd(&M[(kc + 8) * P + vc],     acc2[mi][nj][2]);
                atomicAdd(&M[(kc + 8) * P + vc + 1], acc2[mi][nj][3]);
            }
        }
    }
}

// =====================================================================
// L3: fused qp + out, 4 column tiles per block. grid (4, 32) = 128 blocks.
//  Phase A: qp[128,64] = q @ (D M_batch)     (once per block)
//  Phase B: 4 tiles: out[rows, tile] = qp @ Weff[:, tile]
// =====================================================================
__global__ void __launch_bounds__(256) k_out(float* __restrict__ out)
{
    __shared__ uint32_t AsH[32][136], AsL[32][136];
    __shared__ uint32_t BsH[2][8][72], BsL[2][8][72];

    const int row0 = blockIdx.y * 128;
    const int colBase = blockIdx.x * 256;       // 4 tiles of 64
    const int batch = blockIdx.y >> 4;
    const int tid = threadIdx.x, wid = tid >> 5, lane = tid & 31;
    const int wm = wid & 3, wn = wid >> 2;      // WM=4 x WN=2, warp tile 32x32
    const int g = lane >> 2, t = lane & 3;
    const int n0 = wn * 32;
    const int m_l = tid >> 1, khA = (tid & 1) * 8;
    const int k2b = tid >> 5, n2 = (tid & 31) * 2;
    const float lam = g_lam;

    float acc[2][4][4] = {};

    auto stBr = [&](int buf, const float* r) {
        split2(r[0], r[2], BsH[buf][k2b][n2],   BsL[buf][k2b][n2]);
        split2(r[1], r[3], BsH[buf][k2b][n2+1], BsL[buf][k2b][n2+1]);
    };
    auto compute = [&](int w, int buf) {
        uint32_t bH[4][2], bL[4][2];
        #pragma unroll
        for (int nj = 0; nj < 4; nj++) {
            int nb = n0 + nj * 8 + g;
            bH[nj][0]=BsH[buf][t][nb]; bH[nj][1]=BsH[buf][t+4][nb];
            bL[nj][0]=BsL[buf][t][nb]; bL[nj][1]=BsL[buf][t+4][nb];
        }
        #pragma unroll
        for (int mi = 0; mi < 2; mi++) {
            int mb = wm * 32 + mi * 16 + g;
            uint32_t aH0=AsH[w*8+t  ][mb], aH1=AsH[w*8+t  ][mb+8];
            uint32_t aH2=AsH[w*8+t+4][mb], aH3=AsH[w*8+t+4][mb+8];
            uint32_t aL0=AsL[w*8+t  ][mb], aL1=AsL[w*8+t  ][mb+8];
            uint32_t aL2=AsL[w*8+t+4][mb], aL3=AsL[w*8+t+4][mb+8];
            #pragma unroll
            for (int nj = 0; nj < 4; nj++) {
                MMA_BF16(acc[mi][nj], aH0,aH1,aH2,aH3, bH[nj][0], bH[nj][1]);
                MMA_BF16(acc[mi][nj], aL0,aL1,aL2,aL3, bH[nj][0], bH[nj][1]);
                MMA_BF16(acc[mi][nj], aH0,aH1,aH2,aH3, bL[nj][0], bL[nj][1]);
            }
        }
    };

    // ---- fill As with q (full K=64) ----
    const float* Ap = g_q + (long)(row0 + m_l) * P + khA;
    #pragma unroll
    for (int w = 0; w < 4; w++) {
        float4 v0 = *(const float4*)(Ap + w * 16);
        float4 v1 = *(const float4*)(Ap + w * 16 + 4);
        int kp = w * 8 + (khA >> 1);
        split2(v0.x, v0.y, AsH[kp  ][m_l], AsL[kp  ][m_l]);
        split2(v0.z, v0.w, AsH[kp+1][m_l], AsL[kp+1][m_l]);
        split2(v1.x, v1.y, AsH[kp+2][m_l], AsL[kp+2][m_l]);
        split2(v1.z, v1.w, AsH[kp+3][m_l], AsL[kp+3][m_l]);
    }
    // prefetch D*M windows (phase-A B operand)
    const float* Mp = g_M + batch * P * P;
    float rBm[4][4];
    #pragma unroll
    for (int w = 0; w < 4; w++) {
        int kr = w * 16 + 2 * k2b;
        float2 e0 = *(const float2*)(Mp + (long)kr * P + n2);
        float2 e1 = *(const float2*)(Mp + (long)(kr + 1) * P + n2);
        float s = (kr < 32) ? 0.125f : (-lam * 0.125f);
        rBm[w][0]=e0.x*s; rBm[w][1]=e0.y*s; rBm[w][2]=e1.x*s; rBm[w][3]=e1.y*s;
    }
    __syncthreads();
    #pragma unroll
    for (int w = 0; w < 4; w++) {
        stBr(w & 1, rBm[w]);
        __syncthreads();
        compute(w, w & 1);
    }
    __syncthreads();   // all phase-A computes done before As overwrite

    // ---- store qp fragments into As (C-fragment -> packed A layout) ----
    #pragma unroll
    for (int mi = 0; mi < 2; mi++) {
        int r = wm * 32 + mi * 16 + g;
        #pragma unroll
        for (int nj = 0; nj < 4; nj++) {
            int cl = n0 + nj * 8 + 2 * t;
            split2(acc[mi][nj][0], acc[mi][nj][1], AsH[cl>>1][r],   AsL[cl>>1][r]);
            split2(acc[mi][nj][2], acc[mi][nj][3], AsH[cl>>1][r+8], AsL[cl>>1][r+8]);
            acc[mi][nj][0]=0.f; acc[mi][nj][1]=0.f; acc[mi][nj][2]=0.f; acc[mi][nj][3]=0.f;
        }
    }
    __syncthreads();

    // ---- phase B: 4 column tiles, 16 flattened windows, 1-ahead prefetch ----
    float rB[4];
    auto ldW = [&](int idx, float* r) {
        int ti = idx >> 2, w = idx & 3;
        int kr = w * 16 + 2 * k2b;
        const float* Wp = g_Weff + colBase + ti * 64 + n2;
        float2 e0 = *(const float2*)(Wp + (long)kr * E);
        float2 e1 = *(const float2*)(Wp + (long)(kr + 1) * E);
        r[0]=e0.x; r[1]=e0.y; r[2]=e1.x; r[3]=e1.y;
    };
    ldW(0, rB);
    #pragma unroll 1
    for (int idx = 0; idx < 16; idx++) {
        int buf = idx & 1;
        stBr(buf, rB);
        __syncthreads();
        if (idx < 15) ldW(idx + 1, rB);
        compute(idx & 3, buf);
        if ((idx & 3) == 3) {
            int col0 = colBase + (idx >> 2) * 64;
            #pragma unroll
            for (int mi = 0; mi < 2; mi++) {
                int r = row0 + wm * 32 + mi * 16 + g;
                #pragma unroll
                for (int nj = 0; nj < 4; nj++) {
                    int cl = n0 + nj * 8 + 2 * t;
                    *(float2*)&out[(long)r * E + col0 + cl] =
                        make_float2(acc[mi][nj][0], acc[mi][nj][1]);
                    *(float2*)&out[(long)(r + 8) * E + col0 + cl] =
                        make_float2(acc[mi][nj][2], acc[mi][nj][3]);
                    acc[mi][nj][0]=0.f; acc[mi][nj][1]=0.f;
                    acc[mi][nj][2]=0.f; acc[mi][nj][3]=0.f;
                }
            }
        }
    }
}

// ---------------- launch ----------------
extern "C" void kernel_launch(void* const* d_in, const int* in_sizes, int n_in,
                              void* d_out, int out_size)
{
    const float* x    = (const float*)d_in[0];
    const float* WQ   = (const float*)d_in[1];
    const float* WK   = (const float*)d_in[2];
    const float* WV   = (const float*)d_in[3];
    const float* RW   = (const float*)d_in[4];
    const float* pw   = (const float*)d_in[5];
    const float* pb   = (const float*)d_in[6];
    const float* q1v  = (const float*)d_in[7];
    const float* k1v  = (const float*)d_in[8];
    const float* q2v  = (const float*)d_in[9];
    const float* k2v  = (const float*)d_in[10];
    const float* lam0 = (const float*)d_in[11];
    float* out = (float*)d_out;

    // L0: zero Wf + M
    k_zero<<<193, 256>>>();

    // L1: Weff + lambda + Wf split-K x8
    k_prep<<<641, 256>>>(WQ, WK, WV, pw, RW, q1v, k1v, q2v, k2v, lam0);

    // L2: qkv + fused ktv
    k_qkv<<<dim3(2, 64), 256>>>(x, pb);

    // L3: fused qp + out, 4 col tiles per block
    k_out<<<dim3(4, 32), 256>>>(out);

    (void)in_sizes; (void)n_in; (void)out_size;
}

// round 10
// speedup vs baseline: 1.3047x; 1.1497x over previous
#include <cuda_runtime.h>
#include <cuda_bf16.h>
#include <math.h>
#include <stdint.h>

#define E 1024
#define NH 16
#define P 64
#define BATCH 2
#define SEQ 2048
#define BS (BATCH*SEQ)          // 4096

// ---------------- device scratch ----------------
__device__ float g_lam;
__device__ float g_Wf[E*192];          // [1024,192] fused proj weights
__device__ float g_Weff[P*E];          // [64,1024]
__device__ float g_q[BS*P];            // [4096,64]  q (+bias)
__device__ float g_M[BATCH*P*P];       // [2,64,64]  K^T V

// ---------------- helpers ----------------
__device__ __forceinline__ void split2(float x0, float x1, uint32_t& hi, uint32_t& lo) {
    __nv_bfloat162 h = __floats2bfloat162_rn(x0, x1);
    hi = *(uint32_t*)&h;
    __nv_bfloat162 l = __floats2bfloat162_rn(x0 - __bfloat162float(h.x),
                                             x1 - __bfloat162float(h.y));
    lo = *(uint32_t*)&l;
}

#define MMA_BF16(d, a0,a1,a2,a3, b0,b1) \
    asm volatile("mma.sync.aligned.m16n8k16.row.col.f32.bf16.bf16.f32 " \
        "{%0,%1,%2,%3}, {%4,%5,%6,%7}, {%8,%9}, {%0,%1,%2,%3};" \
        : "+f"(d[0]),"+f"(d[1]),"+f"(d[2]),"+f"(d[3]) \
        : "r"(a0),"r"(a1),"r"(a2),"r"(a3), "r"(b0),"r"(b1))

// =====================================================================
// L0: zero g_Wf (blocks 0..191) + zero g_M (block 192)
// =====================================================================
__global__ void k_zero()
{
    const int bid = blockIdx.x, tid = threadIdx.x;
    if (bid < 192) {
        ((float4*)g_Wf)[bid * 256 + tid] = make_float4(0.f, 0.f, 0.f, 0.f);
    } else {
        for (int i = tid; i < BATCH*P*P; i += 256) g_M[i] = 0.f;
    }
}

// =====================================================================
// L1: blocks [0,256): Weff ; block 256: lambda ;
//     blocks [257,641): Wf split-K x8 (atomicAdd epilogue)
// =====================================================================
__global__ void __launch_bounds__(256) k_prep(
    const float* __restrict__ WQ, const float* __restrict__ WK,
    const float* __restrict__ WV, const float* __restrict__ pw,
    const float* __restrict__ RW,
    const float* __restrict__ q1v, const float* __restrict__ k1v,
    const float* __restrict__ q2v, const float* __restrict__ k2v,
    const float* __restrict__ lam0)
{
    __shared__ uint32_t AsH[8][72], AsL[8][72], BsH[8][72], BsL[8][72];
    const int bid = blockIdx.x;
    const int tid = threadIdx.x;

    if (bid < 256) {
        int idx = bid * 256 + tid;
        int q = idx >> 10, e = idx & 1023;
        float s = 0.f;
        #pragma unroll
        for (int h = 0; h < NH; h++)
            s = fmaf((float)(h + 1), RW[(size_t)((h << 6) + q) * E + e], s);
        g_Weff[idx] = s;
        return;
    }
    if (bid == 256) {
        __shared__ float s1[256], s2[256];
        float a = 0.f, b = 0.f;
        for (int i = tid; i < E; i += 256) {
            a = fmaf(q1v[i], k1v[i], a);
            b = fmaf(q2v[i], k2v[i], b);
        }
        s1[tid] = a; s2[tid] = b; __syncthreads();
        for (int o = 128; o > 0; o >>= 1) {
            if (tid < o) { s1[tid] += s1[tid+o]; s2[tid] += s2[tid+o]; }
            __syncthreads();
        }
        if (tid == 0) g_lam = expf(s1[0]) - expf(s2[0]) + lam0[0];
        return;
    }
    // ---- Wf split-K: 384 blocks = 3 mats x 16 row-tiles x 8 k-chunks ----
    const int r3   = bid - 257;
    const int mat  = r3 >> 7;
    const int chunk = (r3 & 127) >> 4;
    const int row0 = (r3 & 15) * 64;
    const float* A = ((mat == 0) ? WQ : (mat == 1) ? WK : WV) + chunk * 128;
    const float* Bbase = pw + (long)(chunk * 128) * P;
    constexpr int KT = 128;

    const int wid = tid >> 5, lane = tid & 31;
    const int wm = wid & 1, wn = wid >> 1;
    const int g = lane >> 2, t = lane & 3;
    const int n0 = wn * 16;
    const int m_l = tid >> 2, khA = (tid & 3) * 4, khA2 = khA >> 1;
    const int k2b = tid >> 5, n2 = (tid & 31) * 2;

    const float* Ap = A + (long)(row0 + m_l) * E + khA;
    const float* Bp = Bbase + (long)(2 * k2b) * P + n2;

    float rA0[4], rA1[4], rB0[4], rB1[4];
    float acc[2][2][4] = {};

    auto ldA = [&](int k0, float* r) {
        int kk = (k0 < KT) ? k0 : 0;
        float4 v = *(const float4*)(Ap + kk);
        r[0]=v.x; r[1]=v.y; r[2]=v.z; r[3]=v.w;
    };
    auto ldB = [&](int k0, float* r) {
        int kk = (k0 < KT) ? k0 : 0;
        float2 e0 = *(const float2*)(Bp + (long)kk * P);
        float2 e1 = *(const float2*)(Bp + (long)(kk + 1) * P);
        r[0]=e0.x; r[1]=e0.y; r[2]=e1.x; r[3]=e1.y;
    };
    auto stA = [&](const float* r) {
        split2(r[0], r[1], AsH[khA2  ][m_l], AsL[khA2  ][m_l]);
        split2(r[2], r[3], AsH[khA2+1][m_l], AsL[khA2+1][m_l]);
    };
    auto stB = [&](const float* r) {
        split2(r[0], r[2], BsH[k2b][n2],   BsL[k2b][n2]);
        split2(r[1], r[3], BsH[k2b][n2+1], BsL[k2b][n2+1]);
    };
    auto compute = [&]() {
        uint32_t bH[2][2], bL[2][2];
        #pragma unroll
        for (int nj = 0; nj < 2; nj++) {
            int nb = n0 + nj * 8 + g;
            bH[nj][0]=BsH[t][nb]; bH[nj][1]=BsH[t+4][nb];
            bL[nj][0]=BsL[t][nb]; bL[nj][1]=BsL[t+4][nb];
        }
        #pragma unroll
        for (int mi = 0; mi < 2; mi++) {
            int mb = wm * 32 + mi * 16 + g;
            uint32_t aH0=AsH[t][mb],   aH1=AsH[t][mb+8];
            uint32_t aH2=AsH[t+4][mb], aH3=AsH[t+4][mb+8];
            uint32_t aL0=AsL[t][mb],   aL1=AsL[t][mb+8];
            uint32_t aL2=AsL[t+4][mb], aL3=AsL[t+4][mb+8];
            #pragma unroll
            for (int nj = 0; nj < 2; nj++) {
                MMA_BF16(acc[mi][nj], aH0,aH1,aH2,aH3, bH[nj][0], bH[nj][1]);
                MMA_BF16(acc[mi][nj], aL0,aL1,aL2,aL3, bH[nj][0], bH[nj][1]);
                MMA_BF16(acc[mi][nj], aH0,aH1,aH2,aH3, bL[nj][0], bL[nj][1]);
            }
        }
    };

    ldA(0, rA0);  ldB(0, rB0);
    ldA(16, rA1); ldB(16, rB1);
    #pragma unroll 1
    for (int k0 = 0; k0 < KT; k0 += 32) {
        stA(rA0); stB(rB0); __syncthreads();
        ldA(k0 + 32, rA0); ldB(k0 + 32, rB0);
        compute(); __syncthreads();
        stA(rA1); stB(rB1); __syncthreads();
        ldA(k0 + 48, rA1); ldB(k0 + 48, rB1);
        compute(); __syncthreads();
    }
    #pragma unroll
    for (int mi = 0; mi < 2; mi++) {
        int r = row0 + wm * 32 + mi * 16 + g;
        #pragma unroll
        for (int nj = 0; nj < 2; nj++) {
            int cl = n0 + nj * 8 + 2 * t;
            atomicAdd(&g_Wf[(long)r * 192 + mat * 64 + cl],           acc[mi][nj][0]);
            atomicAdd(&g_Wf[(long)r * 192 + mat * 64 + cl + 1],       acc[mi][nj][1]);
            atomicAdd(&g_Wf[(long)(r + 8) * 192 + mat * 64 + cl],     acc[mi][nj][2]);
            atomicAdd(&g_Wf[(long)(r + 8) * 192 + mat * 64 + cl + 1], acc[mi][nj][3]);
        }
    }
}

// =====================================================================
// L2: qkv + fused ktv. grid (2, 64). Deep prefetch (round-7 loop) +
// union'd smem (GEMM staging vs ktv staging) -> 33 KB -> 2 blocks/SM.
// =====================================================================
struct GemmBufs { uint32_t AsH[8][72], AsL[8][72], BsH[8][136], BsL[8][136]; };
struct KtvBufs  { float sKT[64][65], sV[64][65]; };

__global__ void __launch_bounds__(256, 2) k_qkv(
    const float* __restrict__ x, const float* __restrict__ pb)
{
    __shared__ union SU { GemmBufs gb; KtvBufs kb; } su;

    const bool qb = (blockIdx.x == 0);
    const int row0 = blockIdx.y * 64;
    const int batch = blockIdx.y >> 5;
    const int colOff = qb ? 0 : 64;
    const int tid = threadIdx.x, wid = tid >> 5, lane = tid & 31;
    const int wm = wid & 1, wn = wid >> 1;      // WM=2 x WN=4, warp tile 32x32
    const int g = lane >> 2, t = lane & 3;
    const int n0 = wn * 32;
    const int m_l = tid >> 2, khA = (tid & 3) * 4, khA2 = khA >> 1;
    const int k2b = tid >> 6;                   // 0..3
    const int n2  = (tid & 63) * 2;             // 0..126

    const float* Ap = x + (long)(row0 + m_l) * E + khA;
    const float* Bp = g_Wf + colOff + n2;

    float rA0[4], rA1[4], rB0[8], rB1[8];
    float acc[2][4][4] = {};

    auto ldA = [&](int k0, float* r) {
        int kk = (k0 < E) ? k0 : 0;
        float4 v = *(const float4*)(Ap + kk);
        r[0]=v.x; r[1]=v.y; r[2]=v.z; r[3]=v.w;
    };
    auto ldB = [&](int k0, float* r) {
        int kk = (k0 < E) ? k0 : 0;
        float2 e0 = *(const float2*)(Bp + (long)(kk + 2*k2b    ) * 192);
        float2 e1 = *(const float2*)(Bp + (long)(kk + 2*k2b + 1) * 192);
        float2 e2 = *(const float2*)(Bp + (long)(kk + 2*k2b + 8) * 192);
        float2 e3 = *(const float2*)(Bp + (long)(kk + 2*k2b + 9) * 192);
        r[0]=e0.x; r[1]=e0.y; r[2]=e1.x; r[3]=e1.y;
        r[4]=e2.x; r[5]=e2.y; r[6]=e3.x; r[7]=e3.y;
    };
    auto stA = [&](const float* r) {
        split2(r[0], r[1], su.gb.AsH[khA2  ][m_l], su.gb.AsL[khA2  ][m_l]);
        split2(r[2], r[3], su.gb.AsH[khA2+1][m_l], su.gb.AsL[khA2+1][m_l]);
    };
    auto stB = [&](const float* r) {
        split2(r[0], r[2], su.gb.BsH[k2b  ][n2],   su.gb.BsL[k2b  ][n2]);
        split2(r[1], r[3], su.gb.BsH[k2b  ][n2+1], su.gb.BsL[k2b  ][n2+1]);
        split2(r[4], r[6], su.gb.BsH[k2b+4][n2],   su.gb.BsL[k2b+4][n2]);
        split2(r[5], r[7], su.gb.BsH[k2b+4][n2+1], su.gb.BsL[k2b+4][n2+1]);
    };
    auto compute = [&]() {
        uint32_t bH[4][2], bL[4][2];
        #pragma unroll
        for (int nj = 0; nj < 4; nj++) {
            int nb = n0 + nj * 8 + g;
            bH[nj][0]=su.gb.BsH[t][nb]; bH[nj][1]=su.gb.BsH[t+4][nb];
            bL[nj][0]=su.gb.BsL[t][nb]; bL[nj][1]=su.gb.BsL[t+4][nb];
        }
        #pragma unroll
        for (int mi = 0; mi < 2; mi++) {
            int mb = wm * 32 + mi * 16 + g;
            uint32_t aH0=su.gb.AsH[t][mb],   aH1=su.gb.AsH[t][mb+8];
            uint32_t aH2=su.gb.AsH[t+4][mb], aH3=su.gb.AsH[t+4][mb+8];
            uint32_t aL0=su.gb.AsL[t][mb],   aL1=su.gb.AsL[t][mb+8];
            uint32_t aL2=su.gb.AsL[t+4][mb], aL3=su.gb.AsL[t+4][mb+8];
            #pragma unroll
            for (int nj = 0; nj < 4; nj++) {
                MMA_BF16(acc[mi][nj], aH0,aH1,aH2,aH3, bH[nj][0], bH[nj][1]);
                MMA_BF16(acc[mi][nj], aL0,aL1,aL2,aL3, bH[nj][0], bH[nj][1]);
                MMA_BF16(acc[mi][nj], aH0,aH1,aH2,aH3, bL[nj][0], bL[nj][1]);
            }
        }
    };

    ldA(0, rA0);  ldB(0, rB0);
    ldA(16, rA1); ldB(16, rB1);
    #pragma unroll 1
    for (int k0 = 0; k0 < E; k0 += 32) {
        stA(rA0); stB(rB0); __syncthreads();
        ldA(k0 + 32, rA0); ldB(k0 + 32, rB0);
        compute(); __syncthreads();
        stA(rA1); stB(rB1); __syncthreads();
        ldA(k0 + 48, rA1); ldB(k0 + 48, rB1);
        compute(); __syncthreads();
    }
    // loop ends with a sync after the final compute -> safe to reuse union

    if (qb) {
        #pragma unroll
        for (int mi = 0; mi < 2; mi++) {
            int r = row0 + wm * 32 + mi * 16 + g;
            #pragma unroll
            for (int nj = 0; nj < 4; nj++) {
                int cl = n0 + nj * 8 + 2 * t;
                if (cl < 64) {
                    float b0 = pb[cl], b1 = pb[cl + 1];
                    *(float2*)&g_q[(long)r * P + cl] =
                        make_float2(acc[mi][nj][0] + b0, acc[mi][nj][1] + b1);
                    *(float2*)&g_q[(long)(r + 8) * P + cl] =
                        make_float2(acc[mi][nj][2] + b0, acc[mi][nj][3] + b1);
                }
            }
        }
    } else {
        #pragma unroll
        for (int mi = 0; mi < 2; mi++) {
            int tok = wm * 32 + mi * 16 + g;
            #pragma unroll
            for (int nj = 0; nj < 4; nj++) {
                int cl = n0 + nj * 8 + 2 * t;
                float b0 = pb[cl & 63], b1 = pb[(cl + 1) & 63];
                float v00 = acc[mi][nj][0] + b0, v01 = acc[mi][nj][1] + b1;
                float v10 = acc[mi][nj][2] + b0, v11 = acc[mi][nj][3] + b1;
                if (cl < 64) {
                    su.kb.sKT[cl  ][tok]   = v00; su.kb.sKT[cl+1][tok]   = v01;
                    su.kb.sKT[cl  ][tok+8] = v10; su.kb.sKT[cl+1][tok+8] = v11;
                } else {
                    su.kb.sV[tok  ][cl-64] = v00; su.kb.sV[tok  ][cl-63] = v01;
                    su.kb.sV[tok+8][cl-64] = v10; su.kb.sV[tok+8][cl-63] = v11;
                }
            }
        }
        __syncthreads();
        float acc2[2][2][4] = {};
        #pragma unroll
        for (int w = 0; w < 4; w++) {
            int b0k = w * 16;
            uint32_t bH[2][2], bL[2][2];
            #pragma unroll
            for (int nj = 0; nj < 2; nj++) {
                int nb = wn * 16 + nj * 8 + g;
                split2(su.kb.sV[b0k+2*t  ][nb], su.kb.sV[b0k+2*t+1][nb], bH[nj][0], bL[nj][0]);
                split2(su.kb.sV[b0k+2*t+8][nb], su.kb.sV[b0k+2*t+9][nb], bH[nj][1], bL[nj][1]);
            }
            #pragma unroll
            for (int mi = 0; mi < 2; mi++) {
                int mb = wm * 32 + mi * 16 + g;
                uint32_t aH0,aL0,aH1,aL1,aH2,aL2,aH3,aL3;
                split2(su.kb.sKT[mb  ][b0k+2*t  ], su.kb.sKT[mb  ][b0k+2*t+1], aH0, aL0);
                split2(su.kb.sKT[mb+8][b0k+2*t  ], su.kb.sKT[mb+8][b0k+2*t+1], aH1, aL1);
                split2(su.kb.sKT[mb  ][b0k+2*t+8], su.kb.sKT[mb  ][b0k+2*t+9], aH2, aL2);
                split2(su.kb.sKT[mb+8][b0k+2*t+8], su.kb.sKT[mb+8][b0k+2*t+9], aH3, aL3);
                #pragma unroll
                for (int nj = 0; nj < 2; nj++) {
                    MMA_BF16(acc2[mi][nj], aH0,aH1,aH2,aH3, bH[nj][0], bH[nj][1]);
                    MMA_BF16(acc2[mi][nj], aL0,aL1,aL2,aL3, bH[nj][0], bH[nj][1]);
                    MMA_BF16(acc2[mi][nj], aH0,aH1,aH2,aH3, bL[nj][0], bL[nj][1]);
                }
            }
        }
        float* M = g_M + batch * P * P;
        #pragma unroll
        for (int mi = 0; mi < 2; mi++) {
            int kc = wm * 32 + mi * 16 + g;
            #pragma unroll
            for (int nj = 0; nj < 2; nj++) {
                int vc = wn * 16 + nj * 8 + 2 * t;
                atomicAdd(&M[kc * P + vc],           acc2[mi][nj][0]);
                atomicAdd(&M[kc * P + vc + 1],       acc2[mi][nj][1]);
                atomicAdd(&M[(kc + 8) * P + vc],     acc2[mi][nj][2]);
                atomicAdd(&M[(kc + 8) * P + vc + 1], acc2[mi][nj][3]);
            }
        }
    }
}

// =====================================================================
// L3: fused qp + out, BM=64, 4 col tiles per block. grid (4, 64) = 256
// blocks, smem ~28 KB -> 2 blocks/SM.
// =====================================================================
__global__ void __launch_bounds__(256, 2) k_out(float* __restrict__ out)
{
    __shared__ uint32_t AsH[32][72], AsL[32][72];
    __shared__ uint32_t BsH[2][8][72], BsL[2][8][72];

    const int row0 = blockIdx.y * 64;
    const int colBase = blockIdx.x * 256;       // 4 tiles of 64
    const int batch = blockIdx.y >> 5;
    const int tid = threadIdx.x, wid = tid >> 5, lane = tid & 31;
    const int wm = wid & 1, wn = wid >> 1;      // WM=2 x WN=4, warp tile 32x16
    const int g = lane >> 2, t = lane & 3;
    const int n0 = wn * 16;
    const int m_l = tid >> 2, khA = (tid & 3) * 4;
    const int k2b = tid >> 5, n2 = (tid & 31) * 2;
    const float lam = g_lam;

    float acc[2][2][4] = {};

    auto stBr = [&](int buf, const float* r) {
        split2(r[0], r[2], BsH[buf][k2b][n2],   BsL[buf][k2b][n2]);
        split2(r[1], r[3], BsH[buf][k2b][n2+1], BsL[buf][k2b][n2+1]);
    };
    auto compute = [&](int w, int buf) {
        uint32_t bH[2][2], bL[2][2];
        #pragma unroll
        for (int nj = 0; nj < 2; nj++) {
            int nb = n0 + nj * 8 + g;
            bH[nj][0]=BsH[buf][t][nb]; bH[nj][1]=BsH[buf][t+4][nb];
            bL[nj][0]=BsL[buf][t][nb]; bL[nj][1]=BsL[buf][t+4][nb];
        }
        #pragma unroll
        for (int mi = 0; mi < 2; mi++) {
            int mb = wm * 32 + mi * 16 + g;
            uint32_t aH0=AsH[w*8+t  ][mb], aH1=AsH[w*8+t  ][mb+8];
            uint32_t aH2=AsH[w*8+t+4][mb], aH3=AsH[w*8+t+4][mb+8];
            uint32_t aL0=AsL[w*8+t  ][mb], aL1=AsL[w*8+t  ][mb+8];
            uint32_t aL2=AsL[w*8+t+4][mb], aL3=AsL[w*8+t+4][mb+8];
            #pragma unroll
            for (int nj = 0; nj < 2; nj++) {
                MMA_BF16(acc[mi][nj], aH0,aH1,aH2,aH3, bH[nj][0], bH[nj][1]);
                MMA_BF16(acc[mi][nj], aL0,aL1,aL2,aL3, bH[nj][0], bH[nj][1]);
                MMA_BF16(acc[mi][nj], aH0,aH1,aH2,aH3, bL[nj][0], bL[nj][1]);
            }
        }
    };

    // ---- fill As with q rows (full K=64); each thread 16 floats ----
    const float* Ap = g_q + (long)(row0 + m_l) * P + khA;
    #pragma unroll
    for (int w = 0; w < 4; w++) {
        float4 v = *(const float4*)(Ap + w * 16);
        int kp = w * 8 + (khA >> 1);
        split2(v.x, v.y, AsH[kp  ][m_l], AsL[kp  ][m_l]);
        split2(v.z, v.w, AsH[kp+1][m_l], AsL[kp+1][m_l]);
    }
    // prefetch D*M windows (phase-A B operand)
    const float* Mp = g_M + batch * P * P;
    float rBm[4][4];
    #pragma unroll
    for (int w = 0; w < 4; w++) {
        int kr = w * 16 + 2 * k2b;
        float2 e0 = *(const float2*)(Mp + (long)kr * P + n2);
        float2 e1 = *(const float2*)(Mp + (long)(kr + 1) * P + n2);
        float s = (kr < 32) ? 0.125f : (-lam * 0.125f);
        rBm[w][0]=e0.x*s; rBm[w][1]=e0.y*s; rBm[w][2]=e1.x*s; rBm[w][3]=e1.y*s;
    }
    __syncthreads();
    #pragma unroll
    for (int w = 0; w < 4; w++) {
        stBr(w & 1, rBm[w]);
        __syncthreads();
        compute(w, w & 1);
    }
    __syncthreads();   // all phase-A computes done before As overwrite

    // ---- store qp fragments into As (C-fragment -> packed A layout) ----
    #pragma unroll
    for (int mi = 0; mi < 2; mi++) {
        int r = wm * 32 + mi * 16 + g;
        #pragma unroll
        for (int nj = 0; nj < 2; nj++) {
            int cl = n0 + nj * 8 + 2 * t;
            split2(acc[mi][nj][0], acc[mi][nj][1], AsH[cl>>1][r],   AsL[cl>>1][r]);
            split2(acc[mi][nj][2], acc[mi][nj][3], AsH[cl>>1][r+8], AsL[cl>>1][r+8]);
            acc[mi][nj][0]=0.f; acc[mi][nj][1]=0.f; acc[mi][nj][2]=0.f; acc[mi][nj][3]=0.f;
        }
    }
    __syncthreads();

    // ---- phase B: 4 column tiles, 16 flattened windows, 1-ahead prefetch ----
    float rB[4];
    auto ldW = [&](int idx, float* r) {
        int ti = idx >> 2, w = idx & 3;
        int kr = w * 16 + 2 * k2b;
        const float* Wp = g_Weff + colBase + ti * 64 + n2;
        float2 e0 = *(const float2*)(Wp + (long)kr * E);
        float2 e1 = *(const float2*)(Wp + (long)(kr + 1) * E);
        r[0]=e0.x; r[1]=e0.y; r[2]=e1.x; r[3]=e1.y;
    };
    ldW(0, rB);
    #pragma unroll 1
    for (int idx = 0; idx < 16; idx++) {
        int buf = idx & 1;
        stBr(buf, rB);
        __syncthreads();
        if (idx < 15) ldW(idx + 1, rB);
        compute(idx & 3, buf);
        if ((idx & 3) == 3) {
            int col0 = colBase + (idx >> 2) * 64;
            #pragma unroll
            for (int mi = 0; mi < 2; mi++) {
                int r = row0 + wm * 32 + mi * 16 + g;
                #pragma unroll
                for (int nj = 0; nj < 2; nj++) {
                    int cl = n0 + nj * 8 + 2 * t;
                    *(float2*)&out[(long)r * E + col0 + cl] =
                        make_float2(acc[mi][nj][0], acc[mi][nj][1]);
                    *(float2*)&out[(long)(r + 8) * E + col0 + cl] =
                        make_float2(acc[mi][nj][2], acc[mi][nj][3]);
                    acc[mi][nj][0]=0.f; acc[mi][nj][1]=0.f;
                    acc[mi][nj][2]=0.f; acc[mi][nj][3]=0.f;
                }
            }
        }
    }
}

// ---------------- launch ----------------
extern "C" void kernel_launch(void* const* d_in, const int* in_sizes, int n_in,
                              void* d_out, int out_size)
{
    const float* x    = (const float*)d_in[0];
    const float* WQ   = (const float*)d_in[1];
    const float* WK   = (const float*)d_in[2];
    const float* WV   = (const float*)d_in[3];
    const float* RW   = (const float*)d_in[4];
    const float* pw   = (const float*)d_in[5];
    const float* pb   = (const float*)d_in[6];
    const float* q1v  = (const float*)d_in[7];
    const float* k1v  = (const float*)d_in[8];
    const float* q2v  = (const float*)d_in[9];
    const float* k2v  = (const float*)d_in[10];
    const float* lam0 = (const float*)d_in[11];
    float* out = (float*)d_out;

    // L0: zero Wf + M
    k_zero<<<193, 256>>>();

    // L1: Weff + lambda + Wf split-K x8
    k_prep<<<641, 256>>>(WQ, WK, WV, pw, RW, q1v, k1v, q2v, k2v, lam0);

    // L2: qkv + fused ktv (2 blocks/SM)
    k_qkv<<<dim3(2, 64), 256>>>(x, pb);

    // L3: fused qp + out, BM=64, 4 col tiles per block (2 blocks/SM)
    k_out<<<dim3(4, 64), 256>>>(out);

    (void)in_sizes; (void)n_in; (void)out_size;
}

// round 11
// speedup vs baseline: 1.3574x; 1.0403x over previous
#include <cuda_runtime.h>
#include <cuda_bf16.h>
#include <math.h>
#include <stdint.h>

#define E 1024
#define NH 16
#define P 64
#define BATCH 2
#define SEQ 2048
#define BS (BATCH*SEQ)          // 4096

// ---------------- device scratch ----------------
__device__ float g_lam;
__device__ float g_Wf[E*192];          // [1024,192] fused proj weights
__device__ float g_Weff[P*E];          // [64,1024]
__device__ float g_q[BS*P];            // [4096,64]  q (+bias)
__device__ float g_M[BATCH*P*P];       // [2,64,64]  K^T V

// ---------------- helpers ----------------
__device__ __forceinline__ void split2(float x0, float x1, uint32_t& hi, uint32_t& lo) {
    __nv_bfloat162 h = __floats2bfloat162_rn(x0, x1);
    hi = *(uint32_t*)&h;
    __nv_bfloat162 l = __floats2bfloat162_rn(x0 - __bfloat162float(h.x),
                                             x1 - __bfloat162float(h.y));
    lo = *(uint32_t*)&l;
}

#define MMA_BF16(d, a0,a1,a2,a3, b0,b1) \
    asm volatile("mma.sync.aligned.m16n8k16.row.col.f32.bf16.bf16.f32 " \
        "{%0,%1,%2,%3}, {%4,%5,%6,%7}, {%8,%9}, {%0,%1,%2,%3};" \
        : "+f"(d[0]),"+f"(d[1]),"+f"(d[2]),"+f"(d[3]) \
        : "r"(a0),"r"(a1),"r"(a2),"r"(a3), "r"(b0),"r"(b1))

// =====================================================================
// L0: zero g_Wf (blocks 0..191) + zero g_M (block 192)
// =====================================================================
__global__ void k_zero()
{
    const int bid = blockIdx.x, tid = threadIdx.x;
    if (bid < 192) {
        ((float4*)g_Wf)[bid * 256 + tid] = make_float4(0.f, 0.f, 0.f, 0.f);
    } else {
        for (int i = tid; i < BATCH*P*P; i += 256) g_M[i] = 0.f;
    }
}

// =====================================================================
// L1: blocks [0,256): Weff ; block 256: lambda ;
//     blocks [257,641): Wf split-K x8 (atomicAdd epilogue)
// =====================================================================
__global__ void __launch_bounds__(256) k_prep(
    const float* __restrict__ WQ, const float* __restrict__ WK,
    const float* __restrict__ WV, const float* __restrict__ pw,
    const float* __restrict__ RW,
    const float* __restrict__ q1v, const float* __restrict__ k1v,
    const float* __restrict__ q2v, const float* __restrict__ k2v,
    const float* __restrict__ lam0)
{
    __shared__ uint32_t AsH[8][72], AsL[8][72], BsH[8][72], BsL[8][72];
    const int bid = blockIdx.x;
    const int tid = threadIdx.x;

    if (bid < 256) {
        int idx = bid * 256 + tid;
        int q = idx >> 10, e = idx & 1023;
        float s = 0.f;
        #pragma unroll
        for (int h = 0; h < NH; h++)
            s = fmaf((float)(h + 1), RW[(size_t)((h << 6) + q) * E + e], s);
        g_Weff[idx] = s;
        return;
    }
    if (bid == 256) {
        __shared__ float s1[256], s2[256];
        float a = 0.f, b = 0.f;
        for (int i = tid; i < E; i += 256) {
            a = fmaf(q1v[i], k1v[i], a);
            b = fmaf(q2v[i], k2v[i], b);
        }
        s1[tid] = a; s2[tid] = b; __syncthreads();
        for (int o = 128; o > 0; o >>= 1) {
            if (tid < o) { s1[tid] += s1[tid+o]; s2[tid] += s2[tid+o]; }
            __syncthreads();
        }
        if (tid == 0) g_lam = expf(s1[0]) - expf(s2[0]) + lam0[0];
        return;
    }
    // ---- Wf split-K: 384 blocks = 3 mats x 16 row-tiles x 8 k-chunks ----
    const int r3   = bid - 257;
    const int mat  = r3 >> 7;
    const int chunk = (r3 & 127) >> 4;
    const int row0 = (r3 & 15) * 64;
    const float* A = ((mat == 0) ? WQ : (mat == 1) ? WK : WV) + chunk * 128;
    const float* Bbase = pw + (long)(chunk * 128) * P;
    constexpr int KT = 128;

    const int wid = tid >> 5, lane = tid & 31;
    const int wm = wid & 1, wn = wid >> 1;
    const int g = lane >> 2, t = lane & 3;
    const int n0 = wn * 16;
    const int m_l = tid >> 2, khA = (tid & 3) * 4, khA2 = khA >> 1;
    const int k2b = tid >> 5, n2 = (tid & 31) * 2;

    const float* Ap = A + (long)(row0 + m_l) * E + khA;
    const float* Bp = Bbase + (long)(2 * k2b) * P + n2;

    float rA0[4], rA1[4], rB0[4], rB1[4];
    float acc[2][2][4] = {};

    auto ldA = [&](int k0, float* r) {
        int kk = (k0 < KT) ? k0 : 0;
        float4 v = *(const float4*)(Ap + kk);
        r[0]=v.x; r[1]=v.y; r[2]=v.z; r[3]=v.w;
    };
    auto ldB = [&](int k0, float* r) {
        int kk = (k0 < KT) ? k0 : 0;
        float2 e0 = *(const float2*)(Bp + (long)kk * P);
        float2 e1 = *(const float2*)(Bp + (long)(kk + 1) * P);
        r[0]=e0.x; r[1]=e0.y; r[2]=e1.x; r[3]=e1.y;
    };
    auto stA = [&](const float* r) {
        split2(r[0], r[1], AsH[khA2  ][m_l], AsL[khA2  ][m_l]);
        split2(r[2], r[3], AsH[khA2+1][m_l], AsL[khA2+1][m_l]);
    };
    auto stB = [&](const float* r) {
        split2(r[0], r[2], BsH[k2b][n2],   BsL[k2b][n2]);
        split2(r[1], r[3], BsH[k2b][n2+1], BsL[k2b][n2+1]);
    };
    auto compute = [&]() {
        uint32_t bH[2][2], bL[2][2];
        #pragma unroll
        for (int nj = 0; nj < 2; nj++) {
            int nb = n0 + nj * 8 + g;
            bH[nj][0]=BsH[t][nb]; bH[nj][1]=BsH[t+4][nb];
            bL[nj][0]=BsL[t][nb]; bL[nj][1]=BsL[t+4][nb];
        }
        #pragma unroll
        for (int mi = 0; mi < 2; mi++) {
            int mb = wm * 32 + mi * 16 + g;
            uint32_t aH0=AsH[t][mb],   aH1=AsH[t][mb+8];
            uint32_t aH2=AsH[t+4][mb], aH3=AsH[t+4][mb+8];
            uint32_t aL0=AsL[t][mb],   aL1=AsL[t][mb+8];
            uint32_t aL2=AsL[t+4][mb], aL3=AsL[t+4][mb+8];
            #pragma unroll
            for (int nj = 0; nj < 2; nj++) {
                MMA_BF16(acc[mi][nj], aH0,aH1,aH2,aH3, bH[nj][0], bH[nj][1]);
                MMA_BF16(acc[mi][nj], aL0,aL1,aL2,aL3, bH[nj][0], bH[nj][1]);
                MMA_BF16(acc[mi][nj], aH0,aH1,aH2,aH3, bL[nj][0], bL[nj][1]);
            }
        }
    };

    ldA(0, rA0);  ldB(0, rB0);
    ldA(16, rA1); ldB(16, rB1);
    #pragma unroll 1
    for (int k0 = 0; k0 < KT; k0 += 32) {
        stA(rA0); stB(rB0); __syncthreads();
        ldA(k0 + 32, rA0); ldB(k0 + 32, rB0);
        compute(); __syncthreads();
        stA(rA1); stB(rB1); __syncthreads();
        ldA(k0 + 48, rA1); ldB(k0 + 48, rB1);
        compute(); __syncthreads();
    }
    #pragma unroll
    for (int mi = 0; mi < 2; mi++) {
        int r = row0 + wm * 32 + mi * 16 + g;
        #pragma unroll
        for (int nj = 0; nj < 2; nj++) {
            int cl = n0 + nj * 8 + 2 * t;
            atomicAdd(&g_Wf[(long)r * 192 + mat * 64 + cl],           acc[mi][nj][0]);
            atomicAdd(&g_Wf[(long)r * 192 + mat * 64 + cl + 1],       acc[mi][nj][1]);
            atomicAdd(&g_Wf[(long)(r + 8) * 192 + mat * 64 + cl],     acc[mi][nj][2]);
            atomicAdd(&g_Wf[(long)(r + 8) * 192 + mat * 64 + cl + 1], acc[mi][nj][3]);
        }
    }
}

// =====================================================================
// L2: qkv + fused ktv. grid (2, 64). Double-buffered smem (1 sync/window)
// AND 2-deep register prefetch. Union'd with ktv staging.
// =====================================================================
struct GemmBufs { uint32_t AsH[2][8][72], AsL[2][8][72], BsH[2][8][136], BsL[2][8][136]; };
struct KtvBufs  { float sKT[64][65], sV[64][65]; };

__global__ void __launch_bounds__(256, 2) k_qkv(
    const float* __restrict__ x, const float* __restrict__ pb)
{
    __shared__ union SU { GemmBufs gb; KtvBufs kb; } su;

    const bool qb = (blockIdx.x == 0);
    const int row0 = blockIdx.y * 64;
    const int batch = blockIdx.y >> 5;
    const int colOff = qb ? 0 : 64;
    const int tid = threadIdx.x, wid = tid >> 5, lane = tid & 31;
    const int wm = wid & 1, wn = wid >> 1;      // WM=2 x WN=4, warp tile 32x32
    const int g = lane >> 2, t = lane & 3;
    const int n0 = wn * 32;
    const int m_l = tid >> 2, khA = (tid & 3) * 4, khA2 = khA >> 1;
    const int k2b = tid >> 6;                   // 0..3
    const int n2  = (tid & 63) * 2;             // 0..126

    const float* Ap = x + (long)(row0 + m_l) * E + khA;
    const float* Bp = g_Wf + colOff + n2;

    float rA0[4], rA1[4], rB0[8], rB1[8];
    float acc[2][4][4] = {};

    auto ldA = [&](int k0, float* r) {
        int kk = (k0 < E) ? k0 : 0;
        float4 v = *(const float4*)(Ap + kk);
        r[0]=v.x; r[1]=v.y; r[2]=v.z; r[3]=v.w;
    };
    auto ldB = [&](int k0, float* r) {
        int kk = (k0 < E) ? k0 : 0;
        float2 e0 = *(const float2*)(Bp + (long)(kk + 2*k2b    ) * 192);
        float2 e1 = *(const float2*)(Bp + (long)(kk + 2*k2b + 1) * 192);
        float2 e2 = *(const float2*)(Bp + (long)(kk + 2*k2b + 8) * 192);
        float2 e3 = *(const float2*)(Bp + (long)(kk + 2*k2b + 9) * 192);
        r[0]=e0.x; r[1]=e0.y; r[2]=e1.x; r[3]=e1.y;
        r[4]=e2.x; r[5]=e2.y; r[6]=e3.x; r[7]=e3.y;
    };
    auto stA = [&](const float* r, int buf) {
        split2(r[0], r[1], su.gb.AsH[buf][khA2  ][m_l], su.gb.AsL[buf][khA2  ][m_l]);
        split2(r[2], r[3], su.gb.AsH[buf][khA2+1][m_l], su.gb.AsL[buf][khA2+1][m_l]);
    };
    auto stB = [&](const float* r, int buf) {
        split2(r[0], r[2], su.gb.BsH[buf][k2b  ][n2],   su.gb.BsL[buf][k2b  ][n2]);
        split2(r[1], r[3], su.gb.BsH[buf][k2b  ][n2+1], su.gb.BsL[buf][k2b  ][n2+1]);
        split2(r[4], r[6], su.gb.BsH[buf][k2b+4][n2],   su.gb.BsL[buf][k2b+4][n2]);
        split2(r[5], r[7], su.gb.BsH[buf][k2b+4][n2+1], su.gb.BsL[buf][k2b+4][n2+1]);
    };
    auto compute = [&](int buf) {
        uint32_t bH[4][2], bL[4][2];
        #pragma unroll
        for (int nj = 0; nj < 4; nj++) {
            int nb = n0 + nj * 8 + g;
            bH[nj][0]=su.gb.BsH[buf][t][nb]; bH[nj][1]=su.gb.BsH[buf][t+4][nb];
            bL[nj][0]=su.gb.BsL[buf][t][nb]; bL[nj][1]=su.gb.BsL[buf][t+4][nb];
        }
        #pragma unroll
        for (int mi = 0; mi < 2; mi++) {
            int mb = wm * 32 + mi * 16 + g;
            uint32_t aH0=su.gb.AsH[buf][t][mb],   aH1=su.gb.AsH[buf][t][mb+8];
            uint32_t aH2=su.gb.AsH[buf][t+4][mb], aH3=su.gb.AsH[buf][t+4][mb+8];
            uint32_t aL0=su.gb.AsL[buf][t][mb],   aL1=su.gb.AsL[buf][t][mb+8];
            uint32_t aL2=su.gb.AsL[buf][t+4][mb], aL3=su.gb.AsL[buf][t+4][mb+8];
            #pragma unroll
            for (int nj = 0; nj < 4; nj++) {
                MMA_BF16(acc[mi][nj], aH0,aH1,aH2,aH3, bH[nj][0], bH[nj][1]);
                MMA_BF16(acc[mi][nj], aL0,aL1,aL2,aL3, bH[nj][0], bH[nj][1]);
                MMA_BF16(acc[mi][nj], aH0,aH1,aH2,aH3, bL[nj][0], bL[nj][1]);
            }
        }
    };

    // 2-deep prefetch + double-buffered smem: ONE sync per 16-k window.
    // Safety: a store to buf b at window w+2 is ordered after the sync at
    // window w+1, which every thread reaches only after compute(b) at w.
    ldA(0, rA0);  ldB(0, rB0);
    ldA(16, rA1); ldB(16, rB1);
    #pragma unroll 1
    for (int k0 = 0; k0 < E; k0 += 32) {
        stA(rA0, 0); stB(rB0, 0); __syncthreads();
        ldA(k0 + 32, rA0); ldB(k0 + 32, rB0);
        compute(0);
        stA(rA1, 1); stB(rB1, 1); __syncthreads();
        ldA(k0 + 48, rA1); ldB(k0 + 48, rB1);
        compute(1);
    }
    __syncthreads();   // all compute done before union reuse / epilogue

    if (qb) {
        #pragma unroll
        for (int mi = 0; mi < 2; mi++) {
            int r = row0 + wm * 32 + mi * 16 + g;
            #pragma unroll
            for (int nj = 0; nj < 4; nj++) {
                int cl = n0 + nj * 8 + 2 * t;
                if (cl < 64) {
                    float b0 = pb[cl], b1 = pb[cl + 1];
                    *(float2*)&g_q[(long)r * P + cl] =
                        make_float2(acc[mi][nj][0] + b0, acc[mi][nj][1] + b1);
                    *(float2*)&g_q[(long)(r + 8) * P + cl] =
                        make_float2(acc[mi][nj][2] + b0, acc[mi][nj][3] + b1);
                }
            }
        }
    } else {
        #pragma unroll
        for (int mi = 0; mi < 2; mi++) {
            int tok = wm * 32 + mi * 16 + g;
            #pragma unroll
            for (int nj = 0; nj < 4; nj++) {
                int cl = n0 + nj * 8 + 2 * t;
                float b0 = pb[cl & 63], b1 = pb[(cl + 1) & 63];
                float v00 = acc[mi][nj][0] + b0, v01 = acc[mi][nj][1] + b1;
                float v10 = acc[mi][nj][2] + b0, v11 = acc[mi][nj][3] + b1;
                if (cl < 64) {
                    su.kb.sKT[cl  ][tok]   = v00; su.kb.sKT[cl+1][tok]   = v01;
                    su.kb.sKT[cl  ][tok+8] = v10; su.kb.sKT[cl+1][tok+8] = v11;
                } else {
                    su.kb.sV[tok  ][cl-64] = v00; su.kb.sV[tok  ][cl-63] = v01;
                    su.kb.sV[tok+8][cl-64] = v10; su.kb.sV[tok+8][cl-63] = v11;
                }
            }
        }
        __syncthreads();
        float acc2[2][2][4] = {};
        #pragma unroll
        for (int w = 0; w < 4; w++) {
            int b0k = w * 16;
            uint32_t bH[2][2], bL[2][2];
            #pragma unroll
            for (int nj = 0; nj < 2; nj++) {
                int nb = wn * 16 + nj * 8 + g;
                split2(su.kb.sV[b0k+2*t  ][nb], su.kb.sV[b0k+2*t+1][nb], bH[nj][0], bL[nj][0]);
                split2(su.kb.sV[b0k+2*t+8][nb], su.kb.sV[b0k+2*t+9][nb], bH[nj][1], bL[nj][1]);
            }
            #pragma unroll
            for (int mi = 0; mi < 2; mi++) {
                int mb = wm * 32 + mi * 16 + g;
                uint32_t aH0,aL0,aH1,aL1,aH2,aL2,aH3,aL3;
                split2(su.kb.sKT[mb  ][b0k+2*t  ], su.kb.sKT[mb  ][b0k+2*t+1], aH0, aL0);
                split2(su.kb.sKT[mb+8][b0k+2*t  ], su.kb.sKT[mb+8][b0k+2*t+1], aH1, aL1);
                split2(su.kb.sKT[mb  ][b0k+2*t+8], su.kb.sKT[mb  ][b0k+2*t+9], aH2, aL2);
                split2(su.kb.sKT[mb+8][b0k+2*t+8], su.kb.sKT[mb+8][b0k+2*t+9], aH3, aL3);
                #pragma unroll
                for (int nj = 0; nj < 2; nj++) {
                    MMA_BF16(acc2[mi][nj], aH0,aH1,aH2,aH3, bH[nj][0], bH[nj][1]);
                    MMA_BF16(acc2[mi][nj], aL0,aL1,aL2,aL3, bH[nj][0], bH[nj][1]);
                    MMA_BF16(acc2[mi][nj], aH0,aH1,aH2,aH3, bL[nj][0], bL[nj][1]);
                }
            }
        }
        float* M = g_M + batch * P * P;
        #pragma unroll
        for (int mi = 0; mi < 2; mi++) {
            int kc = wm * 32 + mi * 16 + g;
            #pragma unroll
            for (int nj = 0; nj < 2; nj++) {
                int vc = wn * 16 + nj * 8 + 2 * t;
                atomicAdd(&M[kc * P + vc],           acc2[mi][nj][0]);
                atomicAdd(&M[kc * P + vc + 1],       acc2[mi][nj][1]);
                atomicAdd(&M[(kc + 8) * P + vc],     acc2[mi][nj][2]);
                atomicAdd(&M[(kc + 8) * P + vc + 1], acc2[mi][nj][3]);
            }
        }
    }
}

// =====================================================================
// L3: fused qp + out. BM=64. Phase A: qp = q @ (D M) (NJ=2, 64 cols).
// Phase B: BN=128, 2 tiles of 128 cols per block (NJ=4), 8 windows.
// grid (4, 64) = 256 blocks, smem ~36 KB -> 2 blocks/SM.
// =====================================================================
__global__ void __launch_bounds__(256, 2) k_out(float* __restrict__ out)
{
    __shared__ uint32_t AsH[32][72], AsL[32][72];
    __shared__ uint32_t BsH[2][8][136], BsL[2][8][136];

    const int row0 = blockIdx.y * 64;
    const int colBase = blockIdx.x * 256;       // 2 tiles of 128
    const int batch = blockIdx.y >> 5;
    const int tid = threadIdx.x, wid = tid >> 5, lane = tid & 31;
    const int wm = wid & 1, wn = wid >> 1;      // wn: phaseA 16-col, phaseB 32-col
    const int g = lane >> 2, t = lane & 3;
    const int m_l = tid >> 2, khA = (tid & 3) * 4;
    const int k2bA = tid >> 5, n2A = (tid & 31) * 2;   // phase A B-loader
    const int k2bB = tid >> 6, n2B = (tid & 63) * 2;   // phase B B-loader
    const float lam = g_lam;

    // ---- fill As with q rows (full K=64) ----
    const float* Ap = g_q + (long)(row0 + m_l) * P + khA;
    #pragma unroll
    for (int w = 0; w < 4; w++) {
        float4 v = *(const float4*)(Ap + w * 16);
        int kp = w * 8 + (khA >> 1);
        split2(v.x, v.y, AsH[kp  ][m_l], AsL[kp  ][m_l]);
        split2(v.z, v.w, AsH[kp+1][m_l], AsL[kp+1][m_l]);
    }
    // prefetch D*M windows (phase-A B operand)
    const float* Mp = g_M + batch * P * P;
    float rBm[4][4];
    #pragma unroll
    for (int w = 0; w < 4; w++) {
        int kr = w * 16 + 2 * k2bA;
        float2 e0 = *(const float2*)(Mp + (long)kr * P + n2A);
        float2 e1 = *(const float2*)(Mp + (long)(kr + 1) * P + n2A);
        float s = (kr < 32) ? 0.125f : (-lam * 0.125f);
        rBm[w][0]=e0.x*s; rBm[w][1]=e0.y*s; rBm[w][2]=e1.x*s; rBm[w][3]=e1.y*s;
    }
    __syncthreads();

    // ---- phase A: qp = q @ (D M), warp tile 32x16 (NJ=2) ----
    float accA[2][2][4] = {};
    #pragma unroll
    for (int w = 0; w < 4; w++) {
        int buf = w & 1;
        split2(rBm[w][0], rBm[w][2], BsH[buf][k2bA][n2A],   BsL[buf][k2bA][n2A]);
        split2(rBm[w][1], rBm[w][3], BsH[buf][k2bA][n2A+1], BsL[buf][k2bA][n2A+1]);
        __syncthreads();
        uint32_t bH[2][2], bL[2][2];
        #pragma unroll
        for (int nj = 0; nj < 2; nj++) {
            int nb = wn * 16 + nj * 8 + g;
            bH[nj][0]=BsH[buf][t][nb]; bH[nj][1]=BsH[buf][t+4][nb];
            bL[nj][0]=BsL[buf][t][nb]; bL[nj][1]=BsL[buf][t+4][nb];
        }
        #pragma unroll
        for (int mi = 0; mi < 2; mi++) {
            int mb = wm * 32 + mi * 16 + g;
            uint32_t aH0=AsH[w*8+t  ][mb], aH1=AsH[w*8+t  ][mb+8];
            uint32_t aH2=AsH[w*8+t+4][mb], aH3=AsH[w*8+t+4][mb+8];
            uint32_t aL0=AsL[w*8+t  ][mb], aL1=AsL[w*8+t  ][mb+8];
            uint32_t aL2=AsL[w*8+t+4][mb], aL3=AsL[w*8+t+4][mb+8];
            #pragma unroll
            for (int nj = 0; nj < 2; nj++) {
                MMA_BF16(accA[mi][nj], aH0,aH1,aH2,aH3, bH[nj][0], bH[nj][1]);
                MMA_BF16(accA[mi][nj], aL0,aL1,aL2,aL3, bH[nj][0], bH[nj][1]);
                MMA_BF16(accA[mi][nj], aH0,aH1,aH2,aH3, bL[nj][0], bL[nj][1]);
            }
        }
    }
    __syncthreads();   // all phase-A computes done before As overwrite

    // ---- store qp fragments into As (C-fragment -> packed A layout) ----
    #pragma unroll
    for (int mi = 0; mi < 2; mi++) {
        int r = wm * 32 + mi * 16 + g;
        #pragma unroll
        for (int nj = 0; nj < 2; nj++) {
            int cl = wn * 16 + nj * 8 + 2 * t;
            split2(accA[mi][nj][0], accA[mi][nj][1], AsH[cl>>1][r],   AsL[cl>>1][r]);
            split2(accA[mi][nj][2], accA[mi][nj][3], AsH[cl>>1][r+8], AsL[cl>>1][r+8]);
        }
    }
    __syncthreads();

    // ---- phase B: out = qp @ Weff, BN=128, warp tile 32x32 (NJ=4) ----
    float accB[2][4][4] = {};
    float rB[8];
    auto ldW = [&](int idx) {
        int ti = idx >> 2, w = idx & 3;
        int kr = w * 16 + 2 * k2bB;
        const float* Wp = g_Weff + colBase + ti * 128 + n2B;
        float2 e0 = *(const float2*)(Wp + (long)kr * E);
        float2 e1 = *(const float2*)(Wp + (long)(kr + 1) * E);
        float2 e2 = *(const float2*)(Wp + (long)(kr + 8) * E);
        float2 e3 = *(const float2*)(Wp + (long)(kr + 9) * E);
        rB[0]=e0.x; rB[1]=e0.y; rB[2]=e1.x; rB[3]=e1.y;
        rB[4]=e2.x; rB[5]=e2.y; rB[6]=e3.x; rB[7]=e3.y;
    };
    ldW(0);
    #pragma unroll 1
    for (int idx = 0; idx < 8; idx++) {
        int buf = idx & 1;
        split2(rB[0], rB[2], BsH[buf][k2bB][n2B],   BsL[buf][k2bB][n2B]);
        split2(rB[1], rB[3], BsH[buf][k2bB][n2B+1], BsL[buf][k2bB][n2B+1]);
        split2(rB[4], rB[6], BsH[buf][k2bB+4][n2B],   BsL[buf][k2bB+4][n2B]);
        split2(rB[5], rB[7], BsH[buf][k2bB+4][n2B+1], BsL[buf][k2bB+4][n2B+1]);
        __syncthreads();
        if (idx < 7) ldW(idx + 1);
        {
            int w = idx & 3;
            uint32_t bH[4][2], bL[4][2];
            #pragma unroll
            for (int nj = 0; nj < 4; nj++) {
                int nb = wn * 32 + nj * 8 + g;
                bH[nj][0]=BsH[buf][t][nb]; bH[nj][1]=BsH[buf][t+4][nb];
                bL[nj][0]=BsL[buf][t][nb]; bL[nj][1]=BsL[buf][t+4][nb];
            }
            #pragma unroll
            for (int mi = 0; mi < 2; mi++) {
                int mb = wm * 32 + mi * 16 + g;
                uint32_t aH0=AsH[w*8+t  ][mb], aH1=AsH[w*8+t  ][mb+8];
                uint32_t aH2=AsH[w*8+t+4][mb], aH3=AsH[w*8+t+4][mb+8];
                uint32_t aL0=AsL[w*8+t  ][mb], aL1=AsL[w*8+t  ][mb+8];
                uint32_t aL2=AsL[w*8+t+4][mb], aL3=AsL[w*8+t+4][mb+8];
                #pragma unroll
                for (int nj = 0; nj < 4; nj++) {
                    MMA_BF16(accB[mi][nj], aH0,aH1,aH2,aH3, bH[nj][0], bH[nj][1]);
                    MMA_BF16(accB[mi][nj], aL0,aL1,aL2,aL3, bH[nj][0], bH[nj][1]);
                    MMA_BF16(accB[mi][nj], aH0,aH1,aH2,aH3, bL[nj][0], bL[nj][1]);
                }
            }
        }
        if ((idx & 3) == 3) {
            int col0 = colBase + (idx >> 2) * 128;
            #pragma unroll
            for (int mi = 0; mi < 2; mi++) {
                int r = row0 + wm * 32 + mi * 16 + g;
                #pragma unroll
                for (int nj = 0; nj < 4; nj++) {
                    int cl = wn * 32 + nj * 8 + 2 * t;
                    *(float2*)&out[(long)r * E + col0 + cl] =
                        make_float2(accB[mi][nj][0], accB[mi][nj][1]);
                    *(float2*)&out[(long)(r + 8) * E + col0 + cl] =
                        make_float2(accB[mi][nj][2], accB[mi][nj][3]);
                    accB[mi][nj][0]=0.f; accB[mi][nj][1]=0.f;
                    accB[mi][nj][2]=0.f; accB[mi][nj][3]=0.f;
                }
            }
        }
    }
}

// ---------------- launch ----------------
extern "C" void kernel_launch(void* const* d_in, const int* in_sizes, int n_in,
                              void* d_out, int out_size)
{
    const float* x    = (const float*)d_in[0];
    const float* WQ   = (const float*)d_in[1];
    const float* WK   = (const float*)d_in[2];
    const float* WV   = (const float*)d_in[3];
    const float* RW   = (const float*)d_in[4];
    const float* pw   = (const float*)d_in[5];
    const float* pb   = (const float*)d_in[6];
    const float* q1v  = (const float*)d_in[7];
    const float* k1v  = (const float*)d_in[8];
    const float* q2v  = (const float*)d_in[9];
    const float* k2v  = (const float*)d_in[10];
    const float* lam0 = (const float*)d_in[11];
    float* out = (float*)d_out;

    // L0: zero Wf + M
    k_zero<<<193, 256>>>();

    // L1: Weff + lambda + Wf split-K x8
    k_prep<<<641, 256>>>(WQ, WK, WV, pw, RW, q1v, k1v, q2v, k2v, lam0);

    // L2: qkv + fused ktv (1 sync/window, 2-deep prefetch)
    k_qkv<<<dim3(2, 64), 256>>>(x, pb);

    // L3: fused qp + out, phase-B BN=128 (2 tiles per block)
    k_out<<<dim3(4, 64), 256>>>(out);

    (void)in_sizes; (void)n_in; (void)out_size;
}